// round 4
// baseline (speedup 1.0000x reference)
#include <cuda_runtime.h>
#include <math.h>

#define D_MODEL 1024
#define SEQ     2048
#define BATCH   2
#define NH      16
#define HD      64
#define FFN     4096
#define ROWS    (BATCH * SEQ)   /* 4096 */
#define BH      (BATCH * NH)    /* 32 */
#define QKV_LD  (3 * D_MODEL)   /* 3072 */

// ---------------- scratch (static device memory; no allocations) ------------
__device__ float g_qkv[ROWS * QKV_LD];                       // 50 MB
__device__ float g_vals[ROWS * D_MODEL];                     // 16 MB
__device__ float g_attn[ROWS * D_MODEL];
__device__ float g_h[ROWS * D_MODEL];
__device__ float g_ffn1[(size_t)ROWS * FFN];                 // 64 MB
__device__ float g_ffn2[ROWS * D_MODEL];

// ---------------- generic SGEMM: C = A(MxK) @ B(KxN) + bias, opt ReLU -------
// BM=BN=128, BK=8, 256 threads, 8x8 per-thread micro-tile. All dims assumed
// multiples of tile sizes (true for this problem).
template <bool RELU>
__global__ void __launch_bounds__(256) sgemm_bias(const float* __restrict__ A,
                                                  const float* __restrict__ B,
                                                  const float* __restrict__ bias,
                                                  float* __restrict__ C,
                                                  int M, int N, int K) {
    __shared__ float As[8][128];
    __shared__ float Bs[8][128];
    const int tid  = threadIdx.x;
    const int bm   = blockIdx.y << 7;
    const int bn   = blockIdx.x << 7;
    const int arow = tid >> 1, acol = (tid & 1) << 2;
    const int brow = tid >> 5, bcol = (tid & 31) << 2;
    const float* Ap = A + (size_t)(bm + arow) * K + acol;
    const float* Bp = B + (size_t)brow * N + bn + bcol;
    const int tm = (tid >> 4) << 3;
    const int tn = (tid & 15) << 3;

    float acc[8][8] = {};
    for (int k0 = 0; k0 < K; k0 += 8) {
        float4 av = *(const float4*)Ap; Ap += 8;
        float4 bv = *(const float4*)Bp; Bp += (size_t)8 * N;
        As[acol + 0][arow] = av.x;
        As[acol + 1][arow] = av.y;
        As[acol + 2][arow] = av.z;
        As[acol + 3][arow] = av.w;
        *(float4*)&Bs[brow][bcol] = bv;
        __syncthreads();
#pragma unroll
        for (int k = 0; k < 8; k++) {
            float a[8], b[8];
            *(float4*)(a)     = *(const float4*)&As[k][tm];
            *(float4*)(a + 4) = *(const float4*)&As[k][tm + 4];
            *(float4*)(b)     = *(const float4*)&Bs[k][tn];
            *(float4*)(b + 4) = *(const float4*)&Bs[k][tn + 4];
#pragma unroll
            for (int i = 0; i < 8; i++)
#pragma unroll
                for (int j = 0; j < 8; j++)
                    acc[i][j] = fmaf(a[i], b[j], acc[i][j]);
        }
        __syncthreads();
    }

    float4 bias0 = *(const float4*)&bias[bn + tn];
    float4 bias1 = *(const float4*)&bias[bn + tn + 4];
#pragma unroll
    for (int i = 0; i < 8; i++) {
        float4 o0, o1;
        o0.x = acc[i][0] + bias0.x; o0.y = acc[i][1] + bias0.y;
        o0.z = acc[i][2] + bias0.z; o0.w = acc[i][3] + bias0.w;
        o1.x = acc[i][4] + bias1.x; o1.y = acc[i][5] + bias1.y;
        o1.z = acc[i][6] + bias1.z; o1.w = acc[i][7] + bias1.w;
        if (RELU) {
            o0.x = fmaxf(o0.x, 0.f); o0.y = fmaxf(o0.y, 0.f);
            o0.z = fmaxf(o0.z, 0.f); o0.w = fmaxf(o0.w, 0.f);
            o1.x = fmaxf(o1.x, 0.f); o1.y = fmaxf(o1.y, 0.f);
            o1.z = fmaxf(o1.z, 0.f); o1.w = fmaxf(o1.w, 0.f);
        }
        float* cp = C + (size_t)(bm + tm + i) * N + bn + tn;
        *(float4*)cp       = o0;
        *(float4*)(cp + 4) = o1;
    }
}

// ---------------- fused flash attention per (b,h), 64-row Q tiles -----------
// vals[b,s,h*64+d] = softmax(Q K^T / 8) @ V with online softmax.
// smem: Qs/Ks transposed [d][m]; Ks region reused as Ps[m][k]; Vs natural.
// Exactly 48 KB static shared memory.
__global__ void __launch_bounds__(256) attn_flash(const float* __restrict__ qkv,
                                                  float* __restrict__ vals) {
    __shared__ float Qs[64][64];   // [d][m], Q pre-scaled by 0.125
    __shared__ float Ks[64][64];   // [d][n] during S-phase; Ps[m][k] in PV-phase
    __shared__ float Vs[64][64];   // [k][n]
    const int tid = threadIdx.x;
    const int z = blockIdx.z, b = z >> 4, h = z & 15;
    const int m0 = blockIdx.y << 6;
    const size_t base = (size_t)b * SEQ * QKV_LD + (size_t)h * (3 * HD);
    const int tm = ((tid >> 4) & 15) << 2;   // 0..60, rows of S / O
    const int tn = (tid & 15) << 2;          // 0..60, cols of S / O
    const int lr  = tid >> 2;                // 0..63 (transposed-load row)
    const int lc0 = (tid & 3) << 2;          // 0,4,8,12
    const int vr  = tid >> 4;                // 0..15 (natural-load row)
    const int vc  = (tid & 15) << 2;

    // ---- load Q tile transposed, fold in 1/sqrt(64) ----
    {
        const float* Qp = qkv + base + (size_t)(m0 + lr) * QKV_LD + lc0;
#pragma unroll
        for (int it = 0; it < 4; it++) {
            float4 q = *(const float4*)(Qp + it * 16);
            const int c = lc0 + it * 16;
            Qs[c + 0][lr] = q.x * 0.125f;
            Qs[c + 1][lr] = q.y * 0.125f;
            Qs[c + 2][lr] = q.z * 0.125f;
            Qs[c + 3][lr] = q.w * 0.125f;
        }
    }

    float m_run[4], l_run[4];
    float acc[4][4] = {};
#pragma unroll
    for (int i = 0; i < 4; i++) { m_run[i] = -1e30f; l_run[i] = 0.f; }

    for (int kt = 0; kt < SEQ; kt += 64) {
        // ---- load K tile transposed ----
        {
            const float* Kp = qkv + base + HD + (size_t)(kt + lr) * QKV_LD + lc0;
#pragma unroll
            for (int it = 0; it < 4; it++) {
                float4 kv = *(const float4*)(Kp + it * 16);
                const int c = lc0 + it * 16;
                Ks[c + 0][lr] = kv.x;
                Ks[c + 1][lr] = kv.y;
                Ks[c + 2][lr] = kv.z;
                Ks[c + 3][lr] = kv.w;
            }
        }
        // ---- load V tile natural ----
        {
            const float* Vp = qkv + base + 2 * HD + (size_t)(kt + vr) * QKV_LD + vc;
#pragma unroll
            for (int it = 0; it < 4; it++)
                *(float4*)&Vs[vr + it * 16][vc] =
                    *(const float4*)(Vp + (size_t)(it * 16) * QKV_LD);
        }
        __syncthreads();

        // ---- S = (Q/8) K^T, 4x4 per thread ----
        float s[4][4] = {};
#pragma unroll 8
        for (int d = 0; d < 64; d++) {
            float4 a  = *(const float4*)&Qs[d][tm];
            float4 bb = *(const float4*)&Ks[d][tn];
            s[0][0] = fmaf(a.x, bb.x, s[0][0]); s[0][1] = fmaf(a.x, bb.y, s[0][1]);
            s[0][2] = fmaf(a.x, bb.z, s[0][2]); s[0][3] = fmaf(a.x, bb.w, s[0][3]);
            s[1][0] = fmaf(a.y, bb.x, s[1][0]); s[1][1] = fmaf(a.y, bb.y, s[1][1]);
            s[1][2] = fmaf(a.y, bb.z, s[1][2]); s[1][3] = fmaf(a.y, bb.w, s[1][3]);
            s[2][0] = fmaf(a.z, bb.x, s[2][0]); s[2][1] = fmaf(a.z, bb.y, s[2][1]);
            s[2][2] = fmaf(a.z, bb.z, s[2][2]); s[2][3] = fmaf(a.z, bb.w, s[2][3]);
            s[3][0] = fmaf(a.w, bb.x, s[3][0]); s[3][1] = fmaf(a.w, bb.y, s[3][1]);
            s[3][2] = fmaf(a.w, bb.z, s[3][2]); s[3][3] = fmaf(a.w, bb.w, s[3][3]);
        }

        // ---- online softmax update (rows shared by 16-lane groups) ----
#pragma unroll
        for (int i = 0; i < 4; i++) {
            float mm = fmaxf(fmaxf(s[i][0], s[i][1]), fmaxf(s[i][2], s[i][3]));
#pragma unroll
            for (int o = 1; o < 16; o <<= 1)
                mm = fmaxf(mm, __shfl_xor_sync(0xffffffffu, mm, o));
            const float mn = fmaxf(m_run[i], mm);
            const float sc = __expf(m_run[i] - mn);
            l_run[i] *= sc;
            acc[i][0] *= sc; acc[i][1] *= sc; acc[i][2] *= sc; acc[i][3] *= sc;
            float r = 0.f;
#pragma unroll
            for (int j = 0; j < 4; j++) { s[i][j] = __expf(s[i][j] - mn); r += s[i][j]; }
#pragma unroll
            for (int o = 1; o < 16; o <<= 1)
                r += __shfl_xor_sync(0xffffffffu, r, o);
            l_run[i] += r;
            m_run[i] = mn;
        }
        __syncthreads();           // everyone done reading Ks

        // ---- stage P into the Ks region, natural [m][k] layout ----
        float (*Ps)[64] = Ks;
#pragma unroll
        for (int i = 0; i < 4; i++)
#pragma unroll
            for (int j = 0; j < 4; j++)
                Ps[tm + i][tn + j] = s[i][j];
        __syncthreads();

        // ---- O += P @ V ----
#pragma unroll 4
        for (int k4 = 0; k4 < 64; k4 += 4) {
            float4 p0 = *(const float4*)&Ps[tm + 0][k4];
            float4 p1 = *(const float4*)&Ps[tm + 1][k4];
            float4 p2 = *(const float4*)&Ps[tm + 2][k4];
            float4 p3 = *(const float4*)&Ps[tm + 3][k4];
            float4 v0 = *(const float4*)&Vs[k4 + 0][tn];
            float4 v1 = *(const float4*)&Vs[k4 + 1][tn];
            float4 v2 = *(const float4*)&Vs[k4 + 2][tn];
            float4 v3 = *(const float4*)&Vs[k4 + 3][tn];
            acc[0][0] = fmaf(p0.x, v0.x, acc[0][0]); acc[0][1] = fmaf(p0.x, v0.y, acc[0][1]);
            acc[0][2] = fmaf(p0.x, v0.z, acc[0][2]); acc[0][3] = fmaf(p0.x, v0.w, acc[0][3]);
            acc[0][0] = fmaf(p0.y, v1.x, acc[0][0]); acc[0][1] = fmaf(p0.y, v1.y, acc[0][1]);
            acc[0][2] = fmaf(p0.y, v1.z, acc[0][2]); acc[0][3] = fmaf(p0.y, v1.w, acc[0][3]);
            acc[0][0] = fmaf(p0.z, v2.x, acc[0][0]); acc[0][1] = fmaf(p0.z, v2.y, acc[0][1]);
            acc[0][2] = fmaf(p0.z, v2.z, acc[0][2]); acc[0][3] = fmaf(p0.z, v2.w, acc[0][3]);
            acc[0][0] = fmaf(p0.w, v3.x, acc[0][0]); acc[0][1] = fmaf(p0.w, v3.y, acc[0][1]);
            acc[0][2] = fmaf(p0.w, v3.z, acc[0][2]); acc[0][3] = fmaf(p0.w, v3.w, acc[0][3]);
            acc[1][0] = fmaf(p1.x, v0.x, acc[1][0]); acc[1][1] = fmaf(p1.x, v0.y, acc[1][1]);
            acc[1][2] = fmaf(p1.x, v0.z, acc[1][2]); acc[1][3] = fmaf(p1.x, v0.w, acc[1][3]);
            acc[1][0] = fmaf(p1.y, v1.x, acc[1][0]); acc[1][1] = fmaf(p1.y, v1.y, acc[1][1]);
            acc[1][2] = fmaf(p1.y, v1.z, acc[1][2]); acc[1][3] = fmaf(p1.y, v1.w, acc[1][3]);
            acc[1][0] = fmaf(p1.z, v2.x, acc[1][0]); acc[1][1] = fmaf(p1.z, v2.y, acc[1][1]);
            acc[1][2] = fmaf(p1.z, v2.z, acc[1][2]); acc[1][3] = fmaf(p1.z, v2.w, acc[1][3]);
            acc[1][0] = fmaf(p1.w, v3.x, acc[1][0]); acc[1][1] = fmaf(p1.w, v3.y, acc[1][1]);
            acc[1][2] = fmaf(p1.w, v3.z, acc[1][2]); acc[1][3] = fmaf(p1.w, v3.w, acc[1][3]);
            acc[2][0] = fmaf(p2.x, v0.x, acc[2][0]); acc[2][1] = fmaf(p2.x, v0.y, acc[2][1]);
            acc[2][2] = fmaf(p2.x, v0.z, acc[2][2]); acc[2][3] = fmaf(p2.x, v0.w, acc[2][3]);
            acc[2][0] = fmaf(p2.y, v1.x, acc[2][0]); acc[2][1] = fmaf(p2.y, v1.y, acc[2][1]);
            acc[2][2] = fmaf(p2.y, v1.z, acc[2][2]); acc[2][3] = fmaf(p2.y, v1.w, acc[2][3]);
            acc[2][0] = fmaf(p2.z, v2.x, acc[2][0]); acc[2][1] = fmaf(p2.z, v2.y, acc[2][1]);
            acc[2][2] = fmaf(p2.z, v2.z, acc[2][2]); acc[2][3] = fmaf(p2.z, v2.w, acc[2][3]);
            acc[2][0] = fmaf(p2.w, v3.x, acc[2][0]); acc[2][1] = fmaf(p2.w, v3.y, acc[2][1]);
            acc[2][2] = fmaf(p2.w, v3.z, acc[2][2]); acc[2][3] = fmaf(p2.w, v3.w, acc[2][3]);
            acc[3][0] = fmaf(p3.x, v0.x, acc[3][0]); acc[3][1] = fmaf(p3.x, v0.y, acc[3][1]);
            acc[3][2] = fmaf(p3.x, v0.z, acc[3][2]); acc[3][3] = fmaf(p3.x, v0.w, acc[3][3]);
            acc[3][0] = fmaf(p3.y, v1.x, acc[3][0]); acc[3][1] = fmaf(p3.y, v1.y, acc[3][1]);
            acc[3][2] = fmaf(p3.y, v1.z, acc[3][2]); acc[3][3] = fmaf(p3.y, v1.w, acc[3][3]);
            acc[3][0] = fmaf(p3.z, v2.x, acc[3][0]); acc[3][1] = fmaf(p3.z, v2.y, acc[3][1]);
            acc[3][2] = fmaf(p3.z, v2.z, acc[3][2]); acc[3][3] = fmaf(p3.z, v2.w, acc[3][3]);
            acc[3][0] = fmaf(p3.w, v3.x, acc[3][0]); acc[3][1] = fmaf(p3.w, v3.y, acc[3][1]);
            acc[3][2] = fmaf(p3.w, v3.z, acc[3][2]); acc[3][3] = fmaf(p3.w, v3.w, acc[3][3]);
        }
        __syncthreads();           // before next iteration overwrites Ks/Vs
    }

    // ---- finalize: divide by row sums, write [B,S,D] ----
#pragma unroll
    for (int i = 0; i < 4; i++) {
        const float inv = 1.f / l_run[i];
        float4 o;
        o.x = acc[i][0] * inv; o.y = acc[i][1] * inv;
        o.z = acc[i][2] * inv; o.w = acc[i][3] * inv;
        *(float4*)&vals[(size_t)(b * SEQ + m0 + tm + i) * D_MODEL + h * HD + tn] = o;
    }
}

// ---------------- out = LayerNorm(a + res) ----------------------------------
__global__ void __launch_bounds__(256) add_layernorm(const float* __restrict__ a,
                                                     const float* __restrict__ res,
                                                     const float* __restrict__ gamma,
                                                     const float* __restrict__ beta,
                                                     float* __restrict__ out) {
    __shared__ float smA[8];
    __shared__ float smB[8];
    const int row = blockIdx.x, tid = threadIdx.x;
    const float* pa = a + (size_t)row * D_MODEL;
    const float* pr = res + (size_t)row * D_MODEL;

    float v[4];
    float s = 0.f, sq = 0.f;
#pragma unroll
    for (int i = 0; i < 4; i++) {
        v[i] = pa[tid + (i << 8)] + pr[tid + (i << 8)];
        s += v[i];
        sq += v[i] * v[i];
    }
#pragma unroll
    for (int o = 16; o; o >>= 1) {
        s  += __shfl_xor_sync(0xffffffffu, s, o);
        sq += __shfl_xor_sync(0xffffffffu, sq, o);
    }
    if ((tid & 31) == 0) { smA[tid >> 5] = s; smB[tid >> 5] = sq; }
    __syncthreads();
    s  = smA[0] + smA[1] + smA[2] + smA[3] + smA[4] + smA[5] + smA[6] + smA[7];
    sq = smB[0] + smB[1] + smB[2] + smB[3] + smB[4] + smB[5] + smB[6] + smB[7];

    const float mean = s * (1.f / D_MODEL);
    const float var  = sq * (1.f / D_MODEL) - mean * mean;
    const float rstd = rsqrtf(var + 1e-5f);
#pragma unroll
    for (int i = 0; i < 4; i++) {
        const int c = tid + (i << 8);
        out[(size_t)row * D_MODEL + c] = gamma[c] * (v[i] - mean) * rstd + beta[c];
    }
}

// ---------------- launcher --------------------------------------------------
extern "C" void kernel_launch(void* const* d_in, const int* in_sizes, int n_in,
                              void* d_out, int out_size) {
    const float* x      = (const float*)d_in[0];
    const float* W_qkv  = (const float*)d_in[1];
    const float* b_qkv  = (const float*)d_in[2];
    const float* W_o    = (const float*)d_in[3];
    const float* b_o    = (const float*)d_in[4];
    const float* gamma1 = (const float*)d_in[5];
    const float* beta1  = (const float*)d_in[6];
    const float* W1     = (const float*)d_in[7];
    const float* b1     = (const float*)d_in[8];
    const float* W2     = (const float*)d_in[9];
    const float* b2     = (const float*)d_in[10];
    const float* gamma2 = (const float*)d_in[11];
    const float* beta2  = (const float*)d_in[12];
    float* out = (float*)d_out;

    float *qkv, *vals, *attn, *h, *f1, *f2;
    cudaGetSymbolAddress((void**)&qkv,  g_qkv);
    cudaGetSymbolAddress((void**)&vals, g_vals);
    cudaGetSymbolAddress((void**)&attn, g_attn);
    cudaGetSymbolAddress((void**)&h,    g_h);
    cudaGetSymbolAddress((void**)&f1,   g_ffn1);
    cudaGetSymbolAddress((void**)&f2,   g_ffn2);

    // 1. qkv = x @ W_qkv + b_qkv          [4096, 3072]
    sgemm_bias<false><<<dim3(QKV_LD / 128, ROWS / 128), 256>>>(
        x, W_qkv, b_qkv, qkv, ROWS, QKV_LD, D_MODEL);
    // 2-4. fused attention: vals = softmax(Q K^T / 8) @ V   -> [B,S,D]
    attn_flash<<<dim3(1, SEQ / 64, BH), 256>>>(qkv, vals);
    // 5. attn = vals @ W_o + b_o
    sgemm_bias<false><<<dim3(D_MODEL / 128, ROWS / 128), 256>>>(
        vals, W_o, b_o, attn, ROWS, D_MODEL, D_MODEL);
    // 6. h = LN(attn + x)
    add_layernorm<<<ROWS, 256>>>(attn, x, gamma1, beta1, h);
    // 7. f1 = relu(h @ W1 + b1)           [4096, 4096]
    sgemm_bias<true><<<dim3(FFN / 128, ROWS / 128), 256>>>(
        h, W1, b1, f1, ROWS, FFN, D_MODEL);
    // 8. f2 = f1 @ W2 + b2                [4096, 1024]
    sgemm_bias<false><<<dim3(D_MODEL / 128, ROWS / 128), 256>>>(
        f1, W2, b2, f2, ROWS, D_MODEL, FFN);
    // 9. out = LN(f2 + h)
    add_layernorm<<<ROWS, 256>>>(f2, h, gamma2, beta2, out);
}

// round 9
// speedup vs baseline: 1.8070x; 1.8070x over previous
#include <cuda_runtime.h>
#include <math.h>
#include <stdint.h>

#define D_MODEL 1024
#define SEQ     2048
#define BATCH   2
#define NH      16
#define HD      64
#define FFN     4096
#define ROWS    (BATCH * SEQ)   /* 4096 */
#define BH      (BATCH * NH)    /* 32 */
#define QKV_LD  (3 * D_MODEL)   /* 3072 */

// ---------------- scratch (static device memory; no allocations) ------------
__device__ float g_qkv[ROWS * QKV_LD];                       // 50 MB
__device__ float g_vals[ROWS * D_MODEL];
__device__ float g_attn[ROWS * D_MODEL];
__device__ float g_h[ROWS * D_MODEL];
__device__ float g_ffn1[(size_t)ROWS * FFN];                 // 64 MB
__device__ float g_ffn2[ROWS * D_MODEL];

// ---------------- tf32 helpers ----------------------------------------------
__device__ __forceinline__ uint32_t f2tf32(float f) {
    uint32_t u;
    asm("cvt.rna.tf32.f32 %0, %1;" : "=r"(u) : "f"(f));
    return u;
}
__device__ __forceinline__ void mma_tf32(float* d, const uint32_t* a, const uint32_t* b) {
    asm volatile(
        "mma.sync.aligned.m16n8k8.row.col.f32.tf32.tf32.f32 "
        "{%0,%1,%2,%3}, {%4,%5,%6,%7}, {%8,%9}, {%0,%1,%2,%3};"
        : "+f"(d[0]), "+f"(d[1]), "+f"(d[2]), "+f"(d[3])
        : "r"(a[0]), "r"(a[1]), "r"(a[2]), "r"(a[3]), "r"(b[0]), "r"(b[1]));
}

// ---------------- tf32 tensor-core GEMM: C = A[M,K] @ B[K,N] + bias ---------
// CTA tile 128x128, BK=16, 8 warps (2x4), warp tile 64x32 (4x4 m16n8k8 frags).
// A_sm [k][m] / B_sm [k][n], stride 136 floats -> conflict-free frag loads.
#define GSTRIDE 136
template <bool RELU>
__global__ void __launch_bounds__(256) gemm_mma(const float* __restrict__ A,
                                                const float* __restrict__ B,
                                                const float* __restrict__ bias,
                                                float* __restrict__ C,
                                                int M, int N, int K) {
    __shared__ uint32_t As[2][16][GSTRIDE];
    __shared__ uint32_t Bs[2][16][GSTRIDE];
    const int tid = threadIdx.x;
    const int wid = tid >> 5, lane = tid & 31;
    const int bm = blockIdx.y << 7, bn = blockIdx.x << 7;
    const int wm = (wid >> 2) << 6;          // 0 or 64
    const int wn = (wid & 3) << 5;           // 0,32,64,96
    const int r = lane >> 2, c = lane & 3;

    // global-load mapping
    const int arow = tid >> 1;               // 0..127
    const int akq0 = (tid & 1) << 1;         // 0 or 2 (float4 index in k)
    const int brow = (tid << 1) >> 5;        // 0..15
    const int bcol = ((tid << 1) & 31) << 2; // 0..124, 8 consecutive floats

    const float* Abase = A + (size_t)(bm + arow) * K + (akq0 << 2);
    const float* Bbase = B + (size_t)brow * N + bn + bcol;

    float acc[4][4][4] = {};
    float4 av0, av1, bv0, bv1;

    // prologue: stage 0
    av0 = *(const float4*)(Abase);
    av1 = *(const float4*)(Abase + 4);
    bv0 = *(const float4*)(Bbase);
    bv1 = *(const float4*)(Bbase + 4);
    {
        As[0][(akq0 + 0) * 4 + 0][arow] = f2tf32(av0.x);
        As[0][(akq0 + 0) * 4 + 1][arow] = f2tf32(av0.y);
        As[0][(akq0 + 0) * 4 + 2][arow] = f2tf32(av0.z);
        As[0][(akq0 + 0) * 4 + 3][arow] = f2tf32(av0.w);
        As[0][(akq0 + 1) * 4 + 0][arow] = f2tf32(av1.x);
        As[0][(akq0 + 1) * 4 + 1][arow] = f2tf32(av1.y);
        As[0][(akq0 + 1) * 4 + 2][arow] = f2tf32(av1.z);
        As[0][(akq0 + 1) * 4 + 3][arow] = f2tf32(av1.w);
        uint32_t* bp = &Bs[0][brow][bcol];
        bp[0] = f2tf32(bv0.x); bp[1] = f2tf32(bv0.y);
        bp[2] = f2tf32(bv0.z); bp[3] = f2tf32(bv0.w);
        bp[4] = f2tf32(bv1.x); bp[5] = f2tf32(bv1.y);
        bp[6] = f2tf32(bv1.z); bp[7] = f2tf32(bv1.w);
    }

    const int NB = K >> 4;
    for (int kb = 0; kb < NB; kb++) {
        __syncthreads();
        const int nxt = kb + 1;
        if (nxt < NB) {
            const float* Ap = Abase + (nxt << 4);
            const float* Bp = Bbase + (size_t)(nxt << 4) * N;
            av0 = *(const float4*)(Ap);
            av1 = *(const float4*)(Ap + 4);
            bv0 = *(const float4*)(Bp);
            bv1 = *(const float4*)(Bp + 4);
        }

        // ---- compute on buffer kb&1 ----
        const int buf = kb & 1;
#pragma unroll
        for (int g = 0; g < 2; g++) {
            const int k0 = g << 3;
            uint32_t a[4][4], b[4][2];
#pragma unroll
            for (int mt = 0; mt < 4; mt++) {
                const int m = wm + (mt << 4) + r;
                a[mt][0] = As[buf][k0 + c][m];
                a[mt][1] = As[buf][k0 + c][m + 8];
                a[mt][2] = As[buf][k0 + c + 4][m];
                a[mt][3] = As[buf][k0 + c + 4][m + 8];
            }
#pragma unroll
            for (int nt = 0; nt < 4; nt++) {
                const int n = wn + (nt << 3) + r;
                b[nt][0] = Bs[buf][k0 + c][n];
                b[nt][1] = Bs[buf][k0 + c + 4][n];
            }
#pragma unroll
            for (int mt = 0; mt < 4; mt++)
#pragma unroll
                for (int nt = 0; nt < 4; nt++)
                    mma_tf32(acc[mt][nt], a[mt], b[nt]);
        }

        if (nxt < NB) {
            const int nb = nxt & 1;
            As[nb][(akq0 + 0) * 4 + 0][arow] = f2tf32(av0.x);
            As[nb][(akq0 + 0) * 4 + 1][arow] = f2tf32(av0.y);
            As[nb][(akq0 + 0) * 4 + 2][arow] = f2tf32(av0.z);
            As[nb][(akq0 + 0) * 4 + 3][arow] = f2tf32(av0.w);
            As[nb][(akq0 + 1) * 4 + 0][arow] = f2tf32(av1.x);
            As[nb][(akq0 + 1) * 4 + 1][arow] = f2tf32(av1.y);
            As[nb][(akq0 + 1) * 4 + 2][arow] = f2tf32(av1.z);
            As[nb][(akq0 + 1) * 4 + 3][arow] = f2tf32(av1.w);
            uint32_t* bp = &Bs[nb][brow][bcol];
            bp[0] = f2tf32(bv0.x); bp[1] = f2tf32(bv0.y);
            bp[2] = f2tf32(bv0.z); bp[3] = f2tf32(bv0.w);
            bp[4] = f2tf32(bv1.x); bp[5] = f2tf32(bv1.y);
            bp[6] = f2tf32(bv1.z); bp[7] = f2tf32(bv1.w);
        }
    }

    // ---- epilogue: bias (+ReLU), write C ----
#pragma unroll
    for (int mt = 0; mt < 4; mt++) {
        const int row = bm + wm + (mt << 4) + r;
#pragma unroll
        for (int nt = 0; nt < 4; nt++) {
            const int col = bn + wn + (nt << 3) + (c << 1);
            const float b0 = bias[col], b1 = bias[col + 1];
            float v0 = acc[mt][nt][0] + b0;
            float v1 = acc[mt][nt][1] + b1;
            float v2 = acc[mt][nt][2] + b0;
            float v3 = acc[mt][nt][3] + b1;
            if (RELU) {
                v0 = fmaxf(v0, 0.f); v1 = fmaxf(v1, 0.f);
                v2 = fmaxf(v2, 0.f); v3 = fmaxf(v3, 0.f);
            }
            float2 lo = make_float2(v0, v1);
            float2 hi = make_float2(v2, v3);
            *(float2*)&C[(size_t)row * N + col] = lo;
            *(float2*)&C[(size_t)(row + 8) * N + col] = hi;
        }
    }
}

// ---------------- fused flash attention per (b,h), 64-row Q tiles -----------
__global__ void __launch_bounds__(256) attn_flash(const float* __restrict__ qkv,
                                                  float* __restrict__ vals) {
    __shared__ float Qs[64][64];
    __shared__ float Ks[64][64];
    __shared__ float Vs[64][64];
    const int tid = threadIdx.x;
    const int z = blockIdx.z, b = z >> 4, h = z & 15;
    const int m0 = blockIdx.y << 6;
    const size_t base = (size_t)b * SEQ * QKV_LD + (size_t)h * (3 * HD);
    const int tm = ((tid >> 4) & 15) << 2;
    const int tn = (tid & 15) << 2;
    const int lr  = tid >> 2;
    const int lc0 = (tid & 3) << 2;
    const int vr  = tid >> 4;
    const int vc  = (tid & 15) << 2;

    {
        const float* Qp = qkv + base + (size_t)(m0 + lr) * QKV_LD + lc0;
#pragma unroll
        for (int it = 0; it < 4; it++) {
            float4 q = *(const float4*)(Qp + it * 16);
            const int c = lc0 + it * 16;
            Qs[c + 0][lr] = q.x * 0.125f;
            Qs[c + 1][lr] = q.y * 0.125f;
            Qs[c + 2][lr] = q.z * 0.125f;
            Qs[c + 3][lr] = q.w * 0.125f;
        }
    }

    float m_run[4], l_run[4];
    float acc[4][4] = {};
#pragma unroll
    for (int i = 0; i < 4; i++) { m_run[i] = -1e30f; l_run[i] = 0.f; }

    for (int kt = 0; kt < SEQ; kt += 64) {
        {
            const float* Kp = qkv + base + HD + (size_t)(kt + lr) * QKV_LD + lc0;
#pragma unroll
            for (int it = 0; it < 4; it++) {
                float4 kv = *(const float4*)(Kp + it * 16);
                const int c = lc0 + it * 16;
                Ks[c + 0][lr] = kv.x;
                Ks[c + 1][lr] = kv.y;
                Ks[c + 2][lr] = kv.z;
                Ks[c + 3][lr] = kv.w;
            }
        }
        {
            const float* Vp = qkv + base + 2 * HD + (size_t)(kt + vr) * QKV_LD + vc;
#pragma unroll
            for (int it = 0; it < 4; it++)
                *(float4*)&Vs[vr + it * 16][vc] =
                    *(const float4*)(Vp + (size_t)(it * 16) * QKV_LD);
        }
        __syncthreads();

        float s[4][4] = {};
#pragma unroll 8
        for (int d = 0; d < 64; d++) {
            float4 a  = *(const float4*)&Qs[d][tm];
            float4 bb = *(const float4*)&Ks[d][tn];
            s[0][0] = fmaf(a.x, bb.x, s[0][0]); s[0][1] = fmaf(a.x, bb.y, s[0][1]);
            s[0][2] = fmaf(a.x, bb.z, s[0][2]); s[0][3] = fmaf(a.x, bb.w, s[0][3]);
            s[1][0] = fmaf(a.y, bb.x, s[1][0]); s[1][1] = fmaf(a.y, bb.y, s[1][1]);
            s[1][2] = fmaf(a.y, bb.z, s[1][2]); s[1][3] = fmaf(a.y, bb.w, s[1][3]);
            s[2][0] = fmaf(a.z, bb.x, s[2][0]); s[2][1] = fmaf(a.z, bb.y, s[2][1]);
            s[2][2] = fmaf(a.z, bb.z, s[2][2]); s[2][3] = fmaf(a.z, bb.w, s[2][3]);
            s[3][0] = fmaf(a.w, bb.x, s[3][0]); s[3][1] = fmaf(a.w, bb.y, s[3][1]);
            s[3][2] = fmaf(a.w, bb.z, s[3][2]); s[3][3] = fmaf(a.w, bb.w, s[3][3]);
        }

#pragma unroll
        for (int i = 0; i < 4; i++) {
            float mm = fmaxf(fmaxf(s[i][0], s[i][1]), fmaxf(s[i][2], s[i][3]));
#pragma unroll
            for (int o = 1; o < 16; o <<= 1)
                mm = fmaxf(mm, __shfl_xor_sync(0xffffffffu, mm, o));
            const float mn = fmaxf(m_run[i], mm);
            const float sc = __expf(m_run[i] - mn);
            l_run[i] *= sc;
            acc[i][0] *= sc; acc[i][1] *= sc; acc[i][2] *= sc; acc[i][3] *= sc;
            float r = 0.f;
#pragma unroll
            for (int j = 0; j < 4; j++) { s[i][j] = __expf(s[i][j] - mn); r += s[i][j]; }
#pragma unroll
            for (int o = 1; o < 16; o <<= 1)
                r += __shfl_xor_sync(0xffffffffu, r, o);
            l_run[i] += r;
            m_run[i] = mn;
        }
        __syncthreads();

        float (*Ps)[64] = Ks;
#pragma unroll
        for (int i = 0; i < 4; i++)
#pragma unroll
            for (int j = 0; j < 4; j++)
                Ps[tm + i][tn + j] = s[i][j];
        __syncthreads();

#pragma unroll 4
        for (int k4 = 0; k4 < 64; k4 += 4) {
            float4 p0 = *(const float4*)&Ps[tm + 0][k4];
            float4 p1 = *(const float4*)&Ps[tm + 1][k4];
            float4 p2 = *(const float4*)&Ps[tm + 2][k4];
            float4 p3 = *(const float4*)&Ps[tm + 3][k4];
            float4 v0 = *(const float4*)&Vs[k4 + 0][tn];
            float4 v1 = *(const float4*)&Vs[k4 + 1][tn];
            float4 v2 = *(const float4*)&Vs[k4 + 2][tn];
            float4 v3 = *(const float4*)&Vs[k4 + 3][tn];
            acc[0][0] = fmaf(p0.x, v0.x, acc[0][0]); acc[0][1] = fmaf(p0.x, v0.y, acc[0][1]);
            acc[0][2] = fmaf(p0.x, v0.z, acc[0][2]); acc[0][3] = fmaf(p0.x, v0.w, acc[0][3]);
            acc[0][0] = fmaf(p0.y, v1.x, acc[0][0]); acc[0][1] = fmaf(p0.y, v1.y, acc[0][1]);
            acc[0][2] = fmaf(p0.y, v1.z, acc[0][2]); acc[0][3] = fmaf(p0.y, v1.w, acc[0][3]);
            acc[0][0] = fmaf(p0.z, v2.x, acc[0][0]); acc[0][1] = fmaf(p0.z, v2.y, acc[0][1]);
            acc[0][2] = fmaf(p0.z, v2.z, acc[0][2]); acc[0][3] = fmaf(p0.z, v2.w, acc[0][3]);
            acc[0][0] = fmaf(p0.w, v3.x, acc[0][0]); acc[0][1] = fmaf(p0.w, v3.y, acc[0][1]);
            acc[0][2] = fmaf(p0.w, v3.z, acc[0][2]); acc[0][3] = fmaf(p0.w, v3.w, acc[0][3]);
            acc[1][0] = fmaf(p1.x, v0.x, acc[1][0]); acc[1][1] = fmaf(p1.x, v0.y, acc[1][1]);
            acc[1][2] = fmaf(p1.x, v0.z, acc[1][2]); acc[1][3] = fmaf(p1.x, v0.w, acc[1][3]);
            acc[1][0] = fmaf(p1.y, v1.x, acc[1][0]); acc[1][1] = fmaf(p1.y, v1.y, acc[1][1]);
            acc[1][2] = fmaf(p1.y, v1.z, acc[1][2]); acc[1][3] = fmaf(p1.y, v1.w, acc[1][3]);
            acc[1][0] = fmaf(p1.z, v2.x, acc[1][0]); acc[1][1] = fmaf(p1.z, v2.y, acc[1][1]);
            acc[1][2] = fmaf(p1.z, v2.z, acc[1][2]); acc[1][3] = fmaf(p1.z, v2.w, acc[1][3]);
            acc[1][0] = fmaf(p1.w, v3.x, acc[1][0]); acc[1][1] = fmaf(p1.w, v3.y, acc[1][1]);
            acc[1][2] = fmaf(p1.w, v3.z, acc[1][2]); acc[1][3] = fmaf(p1.w, v3.w, acc[1][3]);
            acc[2][0] = fmaf(p2.x, v0.x, acc[2][0]); acc[2][1] = fmaf(p2.x, v0.y, acc[2][1]);
            acc[2][2] = fmaf(p2.x, v0.z, acc[2][2]); acc[2][3] = fmaf(p2.x, v0.w, acc[2][3]);
            acc[2][0] = fmaf(p2.y, v1.x, acc[2][0]); acc[2][1] = fmaf(p2.y, v1.y, acc[2][1]);
            acc[2][2] = fmaf(p2.y, v1.z, acc[2][2]); acc[2][3] = fmaf(p2.y, v1.w, acc[2][3]);
            acc[2][0] = fmaf(p2.z, v2.x, acc[2][0]); acc[2][1] = fmaf(p2.z, v2.y, acc[2][1]);
            acc[2][2] = fmaf(p2.z, v2.z, acc[2][2]); acc[2][3] = fmaf(p2.z, v2.w, acc[2][3]);
            acc[2][0] = fmaf(p2.w, v3.x, acc[2][0]); acc[2][1] = fmaf(p2.w, v3.y, acc[2][1]);
            acc[2][2] = fmaf(p2.w, v3.z, acc[2][2]); acc[2][3] = fmaf(p2.w, v3.w, acc[2][3]);
            acc[3][0] = fmaf(p3.x, v0.x, acc[3][0]); acc[3][1] = fmaf(p3.x, v0.y, acc[3][1]);
            acc[3][2] = fmaf(p3.x, v0.z, acc[3][2]); acc[3][3] = fmaf(p3.x, v0.w, acc[3][3]);
            acc[3][0] = fmaf(p3.y, v1.x, acc[3][0]); acc[3][1] = fmaf(p3.y, v1.y, acc[3][1]);
            acc[3][2] = fmaf(p3.y, v1.z, acc[3][2]); acc[3][3] = fmaf(p3.y, v1.w, acc[3][3]);
            acc[3][0] = fmaf(p3.z, v2.x, acc[3][0]); acc[3][1] = fmaf(p3.z, v2.y, acc[3][1]);
            acc[3][2] = fmaf(p3.z, v2.z, acc[3][2]); acc[3][3] = fmaf(p3.z, v2.w, acc[3][3]);
            acc[3][0] = fmaf(p3.w, v3.x, acc[3][0]); acc[3][1] = fmaf(p3.w, v3.y, acc[3][1]);
            acc[3][2] = fmaf(p3.w, v3.z, acc[3][2]); acc[3][3] = fmaf(p3.w, v3.w, acc[3][3]);
        }
        __syncthreads();
    }

#pragma unroll
    for (int i = 0; i < 4; i++) {
        const float inv = 1.f / l_run[i];
        float4 o;
        o.x = acc[i][0] * inv; o.y = acc[i][1] * inv;
        o.z = acc[i][2] * inv; o.w = acc[i][3] * inv;
        *(float4*)&vals[(size_t)(b * SEQ + m0 + tm + i) * D_MODEL + h * HD + tn] = o;
    }
}

// ---------------- out = LayerNorm(a + res) ----------------------------------
__global__ void __launch_bounds__(256) add_layernorm(const float* __restrict__ a,
                                                     const float* __restrict__ res,
                                                     const float* __restrict__ gamma,
                                                     const float* __restrict__ beta,
                                                     float* __restrict__ out) {
    __shared__ float smA[8];
    __shared__ float smB[8];
    const int row = blockIdx.x, tid = threadIdx.x;
    const float* pa = a + (size_t)row * D_MODEL;
    const float* pr = res + (size_t)row * D_MODEL;

    float v[4];
    float s = 0.f, sq = 0.f;
#pragma unroll
    for (int i = 0; i < 4; i++) {
        v[i] = pa[tid + (i << 8)] + pr[tid + (i << 8)];
        s += v[i];
        sq += v[i] * v[i];
    }
#pragma unroll
    for (int o = 16; o; o >>= 1) {
        s  += __shfl_xor_sync(0xffffffffu, s, o);
        sq += __shfl_xor_sync(0xffffffffu, sq, o);
    }
    if ((tid & 31) == 0) { smA[tid >> 5] = s; smB[tid >> 5] = sq; }
    __syncthreads();
    s  = smA[0] + smA[1] + smA[2] + smA[3] + smA[4] + smA[5] + smA[6] + smA[7];
    sq = smB[0] + smB[1] + smB[2] + smB[3] + smB[4] + smB[5] + smB[6] + smB[7];

    const float mean = s * (1.f / D_MODEL);
    const float var  = sq * (1.f / D_MODEL) - mean * mean;
    const float rstd = rsqrtf(var + 1e-5f);
#pragma unroll
    for (int i = 0; i < 4; i++) {
        const int c = tid + (i << 8);
        out[(size_t)row * D_MODEL + c] = gamma[c] * (v[i] - mean) * rstd + beta[c];
    }
}

// ---------------- launcher --------------------------------------------------
extern "C" void kernel_launch(void* const* d_in, const int* in_sizes, int n_in,
                              void* d_out, int out_size) {
    const float* x      = (const float*)d_in[0];
    const float* W_qkv  = (const float*)d_in[1];
    const float* b_qkv  = (const float*)d_in[2];
    const float* W_o    = (const float*)d_in[3];
    const float* b_o    = (const float*)d_in[4];
    const float* gamma1 = (const float*)d_in[5];
    const float* beta1  = (const float*)d_in[6];
    const float* W1     = (const float*)d_in[7];
    const float* b1     = (const float*)d_in[8];
    const float* W2     = (const float*)d_in[9];
    const float* b2     = (const float*)d_in[10];
    const float* gamma2 = (const float*)d_in[11];
    const float* beta2  = (const float*)d_in[12];
    float* out = (float*)d_out;

    float *qkv, *vals, *attn, *h, *f1, *f2;
    cudaGetSymbolAddress((void**)&qkv,  g_qkv);
    cudaGetSymbolAddress((void**)&vals, g_vals);
    cudaGetSymbolAddress((void**)&attn, g_attn);
    cudaGetSymbolAddress((void**)&h,    g_h);
    cudaGetSymbolAddress((void**)&f1,   g_ffn1);
    cudaGetSymbolAddress((void**)&f2,   g_ffn2);

    // 1. qkv = x @ W_qkv + b_qkv          [4096, 3072]
    gemm_mma<false><<<dim3(QKV_LD / 128, ROWS / 128), 256>>>(
        x, W_qkv, b_qkv, qkv, ROWS, QKV_LD, D_MODEL);
    // 2-4. fused attention
    attn_flash<<<dim3(1, SEQ / 64, BH), 256>>>(qkv, vals);
    // 5. attn = vals @ W_o + b_o
    gemm_mma<false><<<dim3(D_MODEL / 128, ROWS / 128), 256>>>(
        vals, W_o, b_o, attn, ROWS, D_MODEL, D_MODEL);
    // 6. h = LN(attn + x)
    add_layernorm<<<ROWS, 256>>>(attn, x, gamma1, beta1, h);
    // 7. f1 = relu(h @ W1 + b1)           [4096, 4096]
    gemm_mma<true><<<dim3(FFN / 128, ROWS / 128), 256>>>(
        h, W1, b1, f1, ROWS, FFN, D_MODEL);
    // 8. f2 = f1 @ W2 + b2                [4096, 1024]
    gemm_mma<false><<<dim3(D_MODEL / 128, ROWS / 128), 256>>>(
        f1, W2, b2, f2, ROWS, D_MODEL, FFN);
    // 9. out = LN(f2 + h)
    add_layernorm<<<ROWS, 256>>>(f2, h, gamma2, beta2, out);
}

// round 11
// speedup vs baseline: 2.4630x; 1.3630x over previous
#include <cuda_runtime.h>
#include <math.h>
#include <stdint.h>

#define D_MODEL 1024
#define SEQ     2048
#define BATCH   2
#define NH      16
#define HD      64
#define FFN     4096
#define ROWS    (BATCH * SEQ)   /* 4096 */
#define BH      (BATCH * NH)    /* 32 */
#define QKV_LD  (3 * D_MODEL)   /* 3072 */

// ---------------- scratch (static device memory; no allocations) ------------
__device__ float g_qkv[ROWS * QKV_LD];                       // 50 MB
__device__ float g_vals[ROWS * D_MODEL];
__device__ float g_attn[ROWS * D_MODEL];
__device__ float g_h[ROWS * D_MODEL];
__device__ float g_ffn1[(size_t)ROWS * FFN];                 // 64 MB
__device__ float g_ffn2[ROWS * D_MODEL];

// ---------------- tf32 helpers ----------------------------------------------
__device__ __forceinline__ uint32_t f2tf32(float f) {
    uint32_t u;
    asm("cvt.rna.tf32.f32 %0, %1;" : "=r"(u) : "f"(f));
    return u;
}
__device__ __forceinline__ void mma_tf32(float* d, const uint32_t* a, const uint32_t* b) {
    asm volatile(
        "mma.sync.aligned.m16n8k8.row.col.f32.tf32.tf32.f32 "
        "{%0,%1,%2,%3}, {%4,%5,%6,%7}, {%8,%9}, {%0,%1,%2,%3};"
        : "+f"(d[0]), "+f"(d[1]), "+f"(d[2]), "+f"(d[3])
        : "r"(a[0]), "r"(a[1]), "r"(a[2]), "r"(a[3]), "r"(b[0]), "r"(b[1]));
}

// ---------------- tf32 tensor-core GEMM: C = A[M,K] @ B[K,N] + bias ---------
// CTA tile 128x128, BK=16, 8 warps (2x4), warp tile 64x32 (4x4 m16n8k8 frags).
// A_sm [k][m] / B_sm [k][n], stride 136 floats -> conflict-free frag loads.
#define GSTRIDE 136
template <bool RELU>
__global__ void __launch_bounds__(256) gemm_mma(const float* __restrict__ A,
                                                const float* __restrict__ B,
                                                const float* __restrict__ bias,
                                                float* __restrict__ C,
                                                int M, int N, int K) {
    __shared__ uint32_t As[2][16][GSTRIDE];
    __shared__ uint32_t Bs[2][16][GSTRIDE];
    const int tid = threadIdx.x;
    const int wid = tid >> 5, lane = tid & 31;
    const int bm = blockIdx.y << 7, bn = blockIdx.x << 7;
    const int wm = (wid >> 2) << 6;          // 0 or 64
    const int wn = (wid & 3) << 5;           // 0,32,64,96
    const int r = lane >> 2, c = lane & 3;

    // global-load mapping
    const int arow = tid >> 1;               // 0..127
    const int akq0 = (tid & 1) << 1;         // 0 or 2 (float4 index in k)
    const int brow = (tid << 1) >> 5;        // 0..15
    const int bcol = ((tid << 1) & 31) << 2; // 0..124, 8 consecutive floats

    const float* Abase = A + (size_t)(bm + arow) * K + (akq0 << 2);
    const float* Bbase = B + (size_t)brow * N + bn + bcol;

    float acc[4][4][4] = {};
    float4 av0, av1, bv0, bv1;

    // prologue: stage 0
    av0 = *(const float4*)(Abase);
    av1 = *(const float4*)(Abase + 4);
    bv0 = *(const float4*)(Bbase);
    bv1 = *(const float4*)(Bbase + 4);
    {
        As[0][(akq0 + 0) * 4 + 0][arow] = f2tf32(av0.x);
        As[0][(akq0 + 0) * 4 + 1][arow] = f2tf32(av0.y);
        As[0][(akq0 + 0) * 4 + 2][arow] = f2tf32(av0.z);
        As[0][(akq0 + 0) * 4 + 3][arow] = f2tf32(av0.w);
        As[0][(akq0 + 1) * 4 + 0][arow] = f2tf32(av1.x);
        As[0][(akq0 + 1) * 4 + 1][arow] = f2tf32(av1.y);
        As[0][(akq0 + 1) * 4 + 2][arow] = f2tf32(av1.z);
        As[0][(akq0 + 1) * 4 + 3][arow] = f2tf32(av1.w);
        uint32_t* bp = &Bs[0][brow][bcol];
        bp[0] = f2tf32(bv0.x); bp[1] = f2tf32(bv0.y);
        bp[2] = f2tf32(bv0.z); bp[3] = f2tf32(bv0.w);
        bp[4] = f2tf32(bv1.x); bp[5] = f2tf32(bv1.y);
        bp[6] = f2tf32(bv1.z); bp[7] = f2tf32(bv1.w);
    }

    const int NB = K >> 4;
    for (int kb = 0; kb < NB; kb++) {
        __syncthreads();
        const int nxt = kb + 1;
        if (nxt < NB) {
            const float* Ap = Abase + (nxt << 4);
            const float* Bp = Bbase + (size_t)(nxt << 4) * N;
            av0 = *(const float4*)(Ap);
            av1 = *(const float4*)(Ap + 4);
            bv0 = *(const float4*)(Bp);
            bv1 = *(const float4*)(Bp + 4);
        }

        // ---- compute on buffer kb&1 ----
        const int buf = kb & 1;
#pragma unroll
        for (int g = 0; g < 2; g++) {
            const int k0 = g << 3;
            uint32_t a[4][4], b[4][2];
#pragma unroll
            for (int mt = 0; mt < 4; mt++) {
                const int m = wm + (mt << 4) + r;
                a[mt][0] = As[buf][k0 + c][m];
                a[mt][1] = As[buf][k0 + c][m + 8];
                a[mt][2] = As[buf][k0 + c + 4][m];
                a[mt][3] = As[buf][k0 + c + 4][m + 8];
            }
#pragma unroll
            for (int nt = 0; nt < 4; nt++) {
                const int n = wn + (nt << 3) + r;
                b[nt][0] = Bs[buf][k0 + c][n];
                b[nt][1] = Bs[buf][k0 + c + 4][n];
            }
#pragma unroll
            for (int mt = 0; mt < 4; mt++)
#pragma unroll
                for (int nt = 0; nt < 4; nt++)
                    mma_tf32(acc[mt][nt], a[mt], b[nt]);
        }

        if (nxt < NB) {
            const int nb = nxt & 1;
            As[nb][(akq0 + 0) * 4 + 0][arow] = f2tf32(av0.x);
            As[nb][(akq0 + 0) * 4 + 1][arow] = f2tf32(av0.y);
            As[nb][(akq0 + 0) * 4 + 2][arow] = f2tf32(av0.z);
            As[nb][(akq0 + 0) * 4 + 3][arow] = f2tf32(av0.w);
            As[nb][(akq0 + 1) * 4 + 0][arow] = f2tf32(av1.x);
            As[nb][(akq0 + 1) * 4 + 1][arow] = f2tf32(av1.y);
            As[nb][(akq0 + 1) * 4 + 2][arow] = f2tf32(av1.z);
            As[nb][(akq0 + 1) * 4 + 3][arow] = f2tf32(av1.w);
            uint32_t* bp = &Bs[nb][brow][bcol];
            bp[0] = f2tf32(bv0.x); bp[1] = f2tf32(bv0.y);
            bp[2] = f2tf32(bv0.z); bp[3] = f2tf32(bv0.w);
            bp[4] = f2tf32(bv1.x); bp[5] = f2tf32(bv1.y);
            bp[6] = f2tf32(bv1.z); bp[7] = f2tf32(bv1.w);
        }
    }

    // ---- epilogue: bias (+ReLU), write C ----
#pragma unroll
    for (int mt = 0; mt < 4; mt++) {
        const int row = bm + wm + (mt << 4) + r;
#pragma unroll
        for (int nt = 0; nt < 4; nt++) {
            const int col = bn + wn + (nt << 3) + (c << 1);
            const float b0 = bias[col], b1 = bias[col + 1];
            float v0 = acc[mt][nt][0] + b0;
            float v1 = acc[mt][nt][1] + b1;
            float v2 = acc[mt][nt][2] + b0;
            float v3 = acc[mt][nt][3] + b1;
            if (RELU) {
                v0 = fmaxf(v0, 0.f); v1 = fmaxf(v1, 0.f);
                v2 = fmaxf(v2, 0.f); v3 = fmaxf(v3, 0.f);
            }
            float2 lo = make_float2(v0, v1);
            float2 hi = make_float2(v2, v3);
            *(float2*)&C[(size_t)row * N + col] = lo;
            *(float2*)&C[(size_t)(row + 8) * N + col] = hi;
        }
    }
}

// ---------------- tf32 tensor-core flash attention ---------------------------
// Per (b,h): 128-row Q tile per CTA, 256 threads (8 warps, warp w owns rows
// 16w..16w+15). K/V streamed in 64-row tiles. Online softmax warp-local.
// smem (dynamic, 104 KB): Qs[d][m] str136, Ks[d][n] str72, Vs[k][n] str72,
// Ps[k][m] str136. All MMA fragment loads conflict-free.
#define ATTN_SMEM ((64 * 136 + 64 * 72 + 64 * 72 + 64 * 136) * 4)
__global__ void __launch_bounds__(256) attn_flash_mma(const float* __restrict__ qkv,
                                                      float* __restrict__ vals) {
    extern __shared__ uint32_t sm[];
    uint32_t* Qs = sm;                    // [64][136]
    uint32_t* Ks = sm + 64 * 136;         // [64][72]
    uint32_t* Vs = Ks + 64 * 72;          // [64][72]
    uint32_t* Ps = Vs + 64 * 72;          // [64][136]

    const int tid = threadIdx.x;
    const int wid = tid >> 5, lane = tid & 31;
    const int r = lane >> 2, c = lane & 3;
    const int z = blockIdx.z, b = z >> 4, h = z & 15;
    const int m0 = blockIdx.y << 7;       // 128-row Q tile
    const size_t base = (size_t)b * SEQ * QKV_LD + (size_t)h * (3 * HD);
    const int wm = wid << 4;              // warp row offset 0..112

    // ---- load Q tile -> Qs[d][m], fold 1/sqrt(64), tf32 ----
    {
        const int row = tid >> 1;
        const int d0 = (tid & 1) << 5;
        const float* Qp = qkv + base + (size_t)(m0 + row) * QKV_LD + d0;
#pragma unroll
        for (int i = 0; i < 8; i++) {
            float4 q = *(const float4*)(Qp + i * 4);
            const int d = d0 + i * 4;
            Qs[(d + 0) * 136 + row] = f2tf32(q.x * 0.125f);
            Qs[(d + 1) * 136 + row] = f2tf32(q.y * 0.125f);
            Qs[(d + 2) * 136 + row] = f2tf32(q.z * 0.125f);
            Qs[(d + 3) * 136 + row] = f2tf32(q.w * 0.125f);
        }
    }

    float m_run[2] = {-1e30f, -1e30f};    // rows wm+r, wm+r+8
    float l_run[2] = {0.f, 0.f};
    float acc[8][4] = {};

    for (int kt = 0; kt < SEQ; kt += 64) {
        __syncthreads();   // prev PV done reading Vs/Ps; Q store visible (it 0)
        // ---- K tile -> Ks[d][n]; V tile -> Vs[k][n] (tf32) ----
        {
            const int row = tid >> 2;            // 0..63
            const int d0 = (tid & 3) << 4;       // 0,16,32,48
            const float* Kp = qkv + base + HD + (size_t)(kt + row) * QKV_LD + d0;
            const float* Vp = qkv + base + 2 * HD + (size_t)(kt + row) * QKV_LD + d0;
#pragma unroll
            for (int i = 0; i < 4; i++) {
                float4 kv = *(const float4*)(Kp + i * 4);
                const int d = d0 + i * 4;
                Ks[(d + 0) * 72 + row] = f2tf32(kv.x);
                Ks[(d + 1) * 72 + row] = f2tf32(kv.y);
                Ks[(d + 2) * 72 + row] = f2tf32(kv.z);
                Ks[(d + 3) * 72 + row] = f2tf32(kv.w);
                float4 vv = *(const float4*)(Vp + i * 4);
                uint4 pv;
                pv.x = f2tf32(vv.x); pv.y = f2tf32(vv.y);
                pv.z = f2tf32(vv.z); pv.w = f2tf32(vv.w);
                *(uint4*)&Vs[row * 72 + d] = pv;
            }
        }
        __syncthreads();

        // ---- S = (Q/8) K^T : warp rows [wm, wm+16), 8 n-tiles ----
        float s[8][4] = {};
#pragma unroll
        for (int k0 = 0; k0 < 64; k0 += 8) {
            uint32_t a[4];
            a[0] = Qs[(k0 + c) * 136 + wm + r];
            a[1] = Qs[(k0 + c) * 136 + wm + r + 8];
            a[2] = Qs[(k0 + c + 4) * 136 + wm + r];
            a[3] = Qs[(k0 + c + 4) * 136 + wm + r + 8];
#pragma unroll
            for (int nt = 0; nt < 8; nt++) {
                uint32_t bf[2];
                bf[0] = Ks[(k0 + c) * 72 + nt * 8 + r];
                bf[1] = Ks[(k0 + c + 4) * 72 + nt * 8 + r];
                mma_tf32(s[nt], a, bf);
            }
        }

        // ---- online softmax (warp-local rows) ----
        float mA = -1e30f, mB = -1e30f;
#pragma unroll
        for (int nt = 0; nt < 8; nt++) {
            mA = fmaxf(mA, fmaxf(s[nt][0], s[nt][1]));
            mB = fmaxf(mB, fmaxf(s[nt][2], s[nt][3]));
        }
        mA = fmaxf(mA, __shfl_xor_sync(0xffffffffu, mA, 1));
        mA = fmaxf(mA, __shfl_xor_sync(0xffffffffu, mA, 2));
        mB = fmaxf(mB, __shfl_xor_sync(0xffffffffu, mB, 1));
        mB = fmaxf(mB, __shfl_xor_sync(0xffffffffu, mB, 2));
        const float mnA = fmaxf(m_run[0], mA);
        const float mnB = fmaxf(m_run[1], mB);
        const float scA = __expf(m_run[0] - mnA);
        const float scB = __expf(m_run[1] - mnB);
        float rsA = 0.f, rsB = 0.f;
#pragma unroll
        for (int nt = 0; nt < 8; nt++) {
            s[nt][0] = __expf(s[nt][0] - mnA);
            s[nt][1] = __expf(s[nt][1] - mnA);
            s[nt][2] = __expf(s[nt][2] - mnB);
            s[nt][3] = __expf(s[nt][3] - mnB);
            rsA += s[nt][0] + s[nt][1];
            rsB += s[nt][2] + s[nt][3];
            acc[nt][0] *= scA; acc[nt][1] *= scA;
            acc[nt][2] *= scB; acc[nt][3] *= scB;
        }
        rsA += __shfl_xor_sync(0xffffffffu, rsA, 1);
        rsA += __shfl_xor_sync(0xffffffffu, rsA, 2);
        rsB += __shfl_xor_sync(0xffffffffu, rsB, 1);
        rsB += __shfl_xor_sync(0xffffffffu, rsB, 2);
        l_run[0] = l_run[0] * scA + rsA;
        l_run[1] = l_run[1] * scB + rsB;
        m_run[0] = mnA;
        m_run[1] = mnB;

        __syncthreads();   // prev PV reads of Ps complete (also K/V read done)

        // ---- stage P -> Ps[k][m] (tf32) ----
#pragma unroll
        for (int nt = 0; nt < 8; nt++) {
            const int n = nt * 8 + (c << 1);
            Ps[(n + 0) * 136 + wm + r]     = f2tf32(s[nt][0]);
            Ps[(n + 1) * 136 + wm + r]     = f2tf32(s[nt][1]);
            Ps[(n + 0) * 136 + wm + r + 8] = f2tf32(s[nt][2]);
            Ps[(n + 1) * 136 + wm + r + 8] = f2tf32(s[nt][3]);
        }
        __syncthreads();

        // ---- O += P @ V ----
#pragma unroll
        for (int k0 = 0; k0 < 64; k0 += 8) {
            uint32_t a[4];
            a[0] = Ps[(k0 + c) * 136 + wm + r];
            a[1] = Ps[(k0 + c) * 136 + wm + r + 8];
            a[2] = Ps[(k0 + c + 4) * 136 + wm + r];
            a[3] = Ps[(k0 + c + 4) * 136 + wm + r + 8];
#pragma unroll
            for (int nt = 0; nt < 8; nt++) {
                uint32_t bf[2];
                bf[0] = Vs[(k0 + c) * 72 + nt * 8 + r];
                bf[1] = Vs[(k0 + c + 4) * 72 + nt * 8 + r];
                mma_tf32(acc[nt], a, bf);
            }
        }
    }

    // ---- finalize: divide by row sums, write [B,S,D] ----
    const float invA = 1.f / l_run[0];
    const float invB = 1.f / l_run[1];
    const size_t rowA = (size_t)(b * SEQ + m0 + wm + r);
    const size_t rowB = rowA + 8;
#pragma unroll
    for (int nt = 0; nt < 8; nt++) {
        const int col = h * HD + nt * 8 + (c << 1);
        *(float2*)&vals[rowA * D_MODEL + col] =
            make_float2(acc[nt][0] * invA, acc[nt][1] * invA);
        *(float2*)&vals[rowB * D_MODEL + col] =
            make_float2(acc[nt][2] * invB, acc[nt][3] * invB);
    }
}

// ---------------- out = LayerNorm(a + res) ----------------------------------
__global__ void __launch_bounds__(256) add_layernorm(const float* __restrict__ a,
                                                     const float* __restrict__ res,
                                                     const float* __restrict__ gamma,
                                                     const float* __restrict__ beta,
                                                     float* __restrict__ out) {
    __shared__ float smA[8];
    __shared__ float smB[8];
    const int row = blockIdx.x, tid = threadIdx.x;
    const float* pa = a + (size_t)row * D_MODEL;
    const float* pr = res + (size_t)row * D_MODEL;

    float v[4];
    float s = 0.f, sq = 0.f;
#pragma unroll
    for (int i = 0; i < 4; i++) {
        v[i] = pa[tid + (i << 8)] + pr[tid + (i << 8)];
        s += v[i];
        sq += v[i] * v[i];
    }
#pragma unroll
    for (int o = 16; o; o >>= 1) {
        s  += __shfl_xor_sync(0xffffffffu, s, o);
        sq += __shfl_xor_sync(0xffffffffu, sq, o);
    }
    if ((tid & 31) == 0) { smA[tid >> 5] = s; smB[tid >> 5] = sq; }
    __syncthreads();
    s  = smA[0] + smA[1] + smA[2] + smA[3] + smA[4] + smA[5] + smA[6] + smA[7];
    sq = smB[0] + smB[1] + smB[2] + smB[3] + smB[4] + smB[5] + smB[6] + smB[7];

    const float mean = s * (1.f / D_MODEL);
    const float var  = sq * (1.f / D_MODEL) - mean * mean;
    const float rstd = rsqrtf(var + 1e-5f);
#pragma unroll
    for (int i = 0; i < 4; i++) {
        const int c = tid + (i << 8);
        out[(size_t)row * D_MODEL + c] = gamma[c] * (v[i] - mean) * rstd + beta[c];
    }
}

// ---------------- launcher --------------------------------------------------
extern "C" void kernel_launch(void* const* d_in, const int* in_sizes, int n_in,
                              void* d_out, int out_size) {
    const float* x      = (const float*)d_in[0];
    const float* W_qkv  = (const float*)d_in[1];
    const float* b_qkv  = (const float*)d_in[2];
    const float* W_o    = (const float*)d_in[3];
    const float* b_o    = (const float*)d_in[4];
    const float* gamma1 = (const float*)d_in[5];
    const float* beta1  = (const float*)d_in[6];
    const float* W1     = (const float*)d_in[7];
    const float* b1     = (const float*)d_in[8];
    const float* W2     = (const float*)d_in[9];
    const float* b2     = (const float*)d_in[10];
    const float* gamma2 = (const float*)d_in[11];
    const float* beta2  = (const float*)d_in[12];
    float* out = (float*)d_out;

    float *qkv, *vals, *attn, *h, *f1, *f2;
    cudaGetSymbolAddress((void**)&qkv,  g_qkv);
    cudaGetSymbolAddress((void**)&vals, g_vals);
    cudaGetSymbolAddress((void**)&attn, g_attn);
    cudaGetSymbolAddress((void**)&h,    g_h);
    cudaGetSymbolAddress((void**)&f1,   g_ffn1);
    cudaGetSymbolAddress((void**)&f2,   g_ffn2);

    cudaFuncSetAttribute(attn_flash_mma,
                         cudaFuncAttributeMaxDynamicSharedMemorySize, ATTN_SMEM);

    // 1. qkv = x @ W_qkv + b_qkv          [4096, 3072]
    gemm_mma<false><<<dim3(QKV_LD / 128, ROWS / 128), 256>>>(
        x, W_qkv, b_qkv, qkv, ROWS, QKV_LD, D_MODEL);
    // 2-4. fused attention (tf32 MMA)
    attn_flash_mma<<<dim3(1, SEQ / 128, BH), 256, ATTN_SMEM>>>(qkv, vals);
    // 5. attn = vals @ W_o + b_o
    gemm_mma<false><<<dim3(D_MODEL / 128, ROWS / 128), 256>>>(
        vals, W_o, b_o, attn, ROWS, D_MODEL, D_MODEL);
    // 6. h = LN(attn + x)
    add_layernorm<<<ROWS, 256>>>(attn, x, gamma1, beta1, h);
    // 7. f1 = relu(h @ W1 + b1)           [4096, 4096]
    gemm_mma<true><<<dim3(FFN / 128, ROWS / 128), 256>>>(
        h, W1, b1, f1, ROWS, FFN, D_MODEL);
    // 8. f2 = f1 @ W2 + b2                [4096, 1024]
    gemm_mma<false><<<dim3(D_MODEL / 128, ROWS / 128), 256>>>(
        f1, W2, b2, f2, ROWS, D_MODEL, FFN);
    // 9. out = LN(f2 + h)
    add_layernorm<<<ROWS, 256>>>(f2, h, gamma2, beta2, out);
}

// round 12
// speedup vs baseline: 2.9380x; 1.1928x over previous
#include <cuda_runtime.h>
#include <math.h>
#include <stdint.h>

#define D_MODEL 1024
#define SEQ     2048
#define BATCH   2
#define NH      16
#define HD      64
#define FFN     4096
#define ROWS    (BATCH * SEQ)   /* 4096 */
#define BH      (BATCH * NH)    /* 32 */
#define QKV_LD  (3 * D_MODEL)   /* 3072 */

// ---------------- scratch (static device memory; no allocations) ------------
__device__ float g_qkv[ROWS * QKV_LD];                       // 50 MB
__device__ float g_vals[ROWS * D_MODEL];
__device__ float g_attn[ROWS * D_MODEL];
__device__ float g_h[ROWS * D_MODEL];
__device__ float g_ffn1[(size_t)ROWS * FFN];                 // 64 MB
__device__ float g_ffn2[ROWS * D_MODEL];

// ---------------- tf32 / async helpers --------------------------------------
__device__ __forceinline__ uint32_t f2tf32(float f) {
    uint32_t u;
    asm("cvt.rna.tf32.f32 %0, %1;" : "=r"(u) : "f"(f));
    return u;
}
__device__ __forceinline__ void mma_tf32(float* d, const uint32_t* a, const uint32_t* b) {
    asm volatile(
        "mma.sync.aligned.m16n8k8.row.col.f32.tf32.tf32.f32 "
        "{%0,%1,%2,%3}, {%4,%5,%6,%7}, {%8,%9}, {%0,%1,%2,%3};"
        : "+f"(d[0]), "+f"(d[1]), "+f"(d[2]), "+f"(d[3])
        : "r"(a[0]), "r"(a[1]), "r"(a[2]), "r"(a[3]), "r"(b[0]), "r"(b[1]));
}
__device__ __forceinline__ uint32_t smem_u32(const void* p) {
    uint32_t a;
    asm("{ .reg .u64 t; cvta.to.shared.u64 t, %1; cvt.u32.u64 %0, t; }"
        : "=r"(a) : "l"(p));
    return a;
}
__device__ __forceinline__ void cp16(uint32_t dst, const void* src) {
    asm volatile("cp.async.cg.shared.global [%0], [%1], 16;"
                 :: "r"(dst), "l"(src) : "memory");
}
__device__ __forceinline__ void cp_commit() {
    asm volatile("cp.async.commit_group;" ::: "memory");
}
template <int N>
__device__ __forceinline__ void cp_wait() {
    asm volatile("cp.async.wait_group %0;" :: "n"(N) : "memory");
}

// ---------------- tf32 GEMM, cp.async 3-stage pipeline ----------------------
// C = A[M,K] @ B[K,N] + bias (opt ReLU). CTA tile 128x128, BK=32, 8 warps
// (2x4), warp tile 64x32 (4x4 m16n8k8 frags). A smem [m][k] str36,
// B smem [k][n] str136 — both conflict-free for fragment LDS.
#define AST 36
#define BST 136
#define STG_FLOATS (128 * AST + 32 * BST)     /* 8960 floats = 35840 B */
#define GEMM_SMEM (3 * STG_FLOATS * 4)        /* 107520 B */

template <bool RELU>
__global__ void __launch_bounds__(256, 2) gemm_mma(const float* __restrict__ A,
                                                   const float* __restrict__ B,
                                                   const float* __restrict__ bias,
                                                   float* __restrict__ C,
                                                   int M, int N, int K) {
    extern __shared__ float smem[];
    const int tid = threadIdx.x;
    const int wid = tid >> 5, lane = tid & 31;
    const int bm = blockIdx.y << 7, bn = blockIdx.x << 7;
    const int wm = (wid >> 2) << 6;          // 0 or 64
    const int wn = (wid & 3) << 5;           // 0,32,64,96
    const int r = lane >> 2, c = lane & 3;
    const uint32_t smem_base = smem_u32(smem);
    const int NB = K >> 5;

    // cp.async mappings (per stage: A 1024 chunks, B 1024 chunks, 4 each/thread)
    const int arow = tid >> 1;               // reused per i via id
    (void)arow;

    auto issue = [&](int kb) {
        if (kb < NB) {
            const uint32_t As_b = smem_base + (uint32_t)(kb % 3) * (STG_FLOATS * 4);
            const uint32_t Bs_b = As_b + 128 * AST * 4;
#pragma unroll
            for (int i = 0; i < 4; i++) {
                const int id = tid + (i << 8);
                const int row = id >> 3, kc = (id & 7) << 2;
                cp16(As_b + (uint32_t)(row * AST + kc) * 4,
                     A + (size_t)(bm + row) * K + (kb << 5) + kc);
            }
#pragma unroll
            for (int i = 0; i < 4; i++) {
                const int id = tid + (i << 8);
                const int row = id >> 5, nc = (id & 31) << 2;
                cp16(Bs_b + (uint32_t)(row * BST + nc) * 4,
                     B + (size_t)((kb << 5) + row) * N + bn + nc);
            }
        }
        cp_commit();
    };

    float acc[4][4][4] = {};

    issue(0);
    issue(1);

    for (int kb = 0; kb < NB; kb++) {
        cp_wait<1>();
        __syncthreads();
        issue(kb + 2);

        const float* As_s = smem + (kb % 3) * STG_FLOATS;
        const float* Bs_s = As_s + 128 * AST;
#pragma unroll
        for (int g = 0; g < 4; g++) {
            const int k0 = g << 3;
            uint32_t a[4][4], b[4][2];
#pragma unroll
            for (int mt = 0; mt < 4; mt++) {
                const int m = wm + (mt << 4) + r;
                a[mt][0] = f2tf32(As_s[m * AST + k0 + c]);
                a[mt][1] = f2tf32(As_s[(m + 8) * AST + k0 + c]);
                a[mt][2] = f2tf32(As_s[m * AST + k0 + c + 4]);
                a[mt][3] = f2tf32(As_s[(m + 8) * AST + k0 + c + 4]);
            }
#pragma unroll
            for (int nt = 0; nt < 4; nt++) {
                const int n = wn + (nt << 3) + r;
                b[nt][0] = f2tf32(Bs_s[(k0 + c) * BST + n]);
                b[nt][1] = f2tf32(Bs_s[(k0 + c + 4) * BST + n]);
            }
#pragma unroll
            for (int mt = 0; mt < 4; mt++)
#pragma unroll
                for (int nt = 0; nt < 4; nt++)
                    mma_tf32(acc[mt][nt], a[mt], b[nt]);
        }
    }

    // ---- epilogue: bias (+ReLU), write C ----
#pragma unroll
    for (int mt = 0; mt < 4; mt++) {
        const int row = bm + wm + (mt << 4) + r;
#pragma unroll
        for (int nt = 0; nt < 4; nt++) {
            const int col = bn + wn + (nt << 3) + (c << 1);
            const float b0 = bias[col], b1 = bias[col + 1];
            float v0 = acc[mt][nt][0] + b0;
            float v1 = acc[mt][nt][1] + b1;
            float v2 = acc[mt][nt][2] + b0;
            float v3 = acc[mt][nt][3] + b1;
            if (RELU) {
                v0 = fmaxf(v0, 0.f); v1 = fmaxf(v1, 0.f);
                v2 = fmaxf(v2, 0.f); v3 = fmaxf(v3, 0.f);
            }
            *(float2*)&C[(size_t)row * N + col] = make_float2(v0, v1);
            *(float2*)&C[(size_t)(row + 8) * N + col] = make_float2(v2, v3);
        }
    }
}

// ---------------- tf32 tensor-core flash attention ---------------------------
// Per (b,h): 128-row Q tile per CTA, 256 threads (8 warps, warp w owns rows
// 16w..16w+15). K/V streamed in 64-row tiles. Online softmax warp-local.
#define ATTN_SMEM ((64 * 136 + 64 * 72 + 64 * 72 + 64 * 136) * 4)
__global__ void __launch_bounds__(256) attn_flash_mma(const float* __restrict__ qkv,
                                                      float* __restrict__ vals) {
    extern __shared__ uint32_t sm[];
    uint32_t* Qs = sm;                    // [64][136]
    uint32_t* Ks = sm + 64 * 136;         // [64][72]
    uint32_t* Vs = Ks + 64 * 72;          // [64][72]
    uint32_t* Ps = Vs + 64 * 72;          // [64][136]

    const int tid = threadIdx.x;
    const int wid = tid >> 5, lane = tid & 31;
    const int r = lane >> 2, c = lane & 3;
    const int z = blockIdx.z, b = z >> 4, h = z & 15;
    const int m0 = blockIdx.y << 7;       // 128-row Q tile
    const size_t base = (size_t)b * SEQ * QKV_LD + (size_t)h * (3 * HD);
    const int wm = wid << 4;              // warp row offset 0..112

    // ---- load Q tile -> Qs[d][m], fold 1/sqrt(64), tf32 ----
    {
        const int row = tid >> 1;
        const int d0 = (tid & 1) << 5;
        const float* Qp = qkv + base + (size_t)(m0 + row) * QKV_LD + d0;
#pragma unroll
        for (int i = 0; i < 8; i++) {
            float4 q = *(const float4*)(Qp + i * 4);
            const int d = d0 + i * 4;
            Qs[(d + 0) * 136 + row] = f2tf32(q.x * 0.125f);
            Qs[(d + 1) * 136 + row] = f2tf32(q.y * 0.125f);
            Qs[(d + 2) * 136 + row] = f2tf32(q.z * 0.125f);
            Qs[(d + 3) * 136 + row] = f2tf32(q.w * 0.125f);
        }
    }

    float m_run[2] = {-1e30f, -1e30f};    // rows wm+r, wm+r+8
    float l_run[2] = {0.f, 0.f};
    float acc[8][4] = {};

    for (int kt = 0; kt < SEQ; kt += 64) {
        __syncthreads();   // prev PV done reading Vs/Ps; Q store visible (it 0)
        // ---- K tile -> Ks[d][n]; V tile -> Vs[k][n] (tf32) ----
        {
            const int row = tid >> 2;            // 0..63
            const int d0 = (tid & 3) << 4;       // 0,16,32,48
            const float* Kp = qkv + base + HD + (size_t)(kt + row) * QKV_LD + d0;
            const float* Vp = qkv + base + 2 * HD + (size_t)(kt + row) * QKV_LD + d0;
#pragma unroll
            for (int i = 0; i < 4; i++) {
                float4 kv = *(const float4*)(Kp + i * 4);
                const int d = d0 + i * 4;
                Ks[(d + 0) * 72 + row] = f2tf32(kv.x);
                Ks[(d + 1) * 72 + row] = f2tf32(kv.y);
                Ks[(d + 2) * 72 + row] = f2tf32(kv.z);
                Ks[(d + 3) * 72 + row] = f2tf32(kv.w);
                float4 vv = *(const float4*)(Vp + i * 4);
                uint4 pv;
                pv.x = f2tf32(vv.x); pv.y = f2tf32(vv.y);
                pv.z = f2tf32(vv.z); pv.w = f2tf32(vv.w);
                *(uint4*)&Vs[row * 72 + d] = pv;
            }
        }
        __syncthreads();

        // ---- S = (Q/8) K^T : warp rows [wm, wm+16), 8 n-tiles ----
        float s[8][4] = {};
#pragma unroll
        for (int k0 = 0; k0 < 64; k0 += 8) {
            uint32_t a[4];
            a[0] = Qs[(k0 + c) * 136 + wm + r];
            a[1] = Qs[(k0 + c) * 136 + wm + r + 8];
            a[2] = Qs[(k0 + c + 4) * 136 + wm + r];
            a[3] = Qs[(k0 + c + 4) * 136 + wm + r + 8];
#pragma unroll
            for (int nt = 0; nt < 8; nt++) {
                uint32_t bf[2];
                bf[0] = Ks[(k0 + c) * 72 + nt * 8 + r];
                bf[1] = Ks[(k0 + c + 4) * 72 + nt * 8 + r];
                mma_tf32(s[nt], a, bf);
            }
        }

        // ---- online softmax (warp-local rows) ----
        float mA = -1e30f, mB = -1e30f;
#pragma unroll
        for (int nt = 0; nt < 8; nt++) {
            mA = fmaxf(mA, fmaxf(s[nt][0], s[nt][1]));
            mB = fmaxf(mB, fmaxf(s[nt][2], s[nt][3]));
        }
        mA = fmaxf(mA, __shfl_xor_sync(0xffffffffu, mA, 1));
        mA = fmaxf(mA, __shfl_xor_sync(0xffffffffu, mA, 2));
        mB = fmaxf(mB, __shfl_xor_sync(0xffffffffu, mB, 1));
        mB = fmaxf(mB, __shfl_xor_sync(0xffffffffu, mB, 2));
        const float mnA = fmaxf(m_run[0], mA);
        const float mnB = fmaxf(m_run[1], mB);
        const float scA = __expf(m_run[0] - mnA);
        const float scB = __expf(m_run[1] - mnB);
        float rsA = 0.f, rsB = 0.f;
#pragma unroll
        for (int nt = 0; nt < 8; nt++) {
            s[nt][0] = __expf(s[nt][0] - mnA);
            s[nt][1] = __expf(s[nt][1] - mnA);
            s[nt][2] = __expf(s[nt][2] - mnB);
            s[nt][3] = __expf(s[nt][3] - mnB);
            rsA += s[nt][0] + s[nt][1];
            rsB += s[nt][2] + s[nt][3];
            acc[nt][0] *= scA; acc[nt][1] *= scA;
            acc[nt][2] *= scB; acc[nt][3] *= scB;
        }
        rsA += __shfl_xor_sync(0xffffffffu, rsA, 1);
        rsA += __shfl_xor_sync(0xffffffffu, rsA, 2);
        rsB += __shfl_xor_sync(0xffffffffu, rsB, 1);
        rsB += __shfl_xor_sync(0xffffffffu, rsB, 2);
        l_run[0] = l_run[0] * scA + rsA;
        l_run[1] = l_run[1] * scB + rsB;
        m_run[0] = mnA;
        m_run[1] = mnB;

        __syncthreads();   // prev PV reads of Ps complete (also K/V read done)

        // ---- stage P -> Ps[k][m] (tf32) ----
#pragma unroll
        for (int nt = 0; nt < 8; nt++) {
            const int n = nt * 8 + (c << 1);
            Ps[(n + 0) * 136 + wm + r]     = f2tf32(s[nt][0]);
            Ps[(n + 1) * 136 + wm + r]     = f2tf32(s[nt][1]);
            Ps[(n + 0) * 136 + wm + r + 8] = f2tf32(s[nt][2]);
            Ps[(n + 1) * 136 + wm + r + 8] = f2tf32(s[nt][3]);
        }
        __syncthreads();

        // ---- O += P @ V ----
#pragma unroll
        for (int k0 = 0; k0 < 64; k0 += 8) {
            uint32_t a[4];
            a[0] = Ps[(k0 + c) * 136 + wm + r];
            a[1] = Ps[(k0 + c) * 136 + wm + r + 8];
            a[2] = Ps[(k0 + c + 4) * 136 + wm + r];
            a[3] = Ps[(k0 + c + 4) * 136 + wm + r + 8];
#pragma unroll
            for (int nt = 0; nt < 8; nt++) {
                uint32_t bf[2];
                bf[0] = Vs[(k0 + c) * 72 + nt * 8 + r];
                bf[1] = Vs[(k0 + c + 4) * 72 + nt * 8 + r];
                mma_tf32(acc[nt], a, bf);
            }
        }
    }

    // ---- finalize: divide by row sums, write [B,S,D] ----
    const float invA = 1.f / l_run[0];
    const float invB = 1.f / l_run[1];
    const size_t rowA = (size_t)(b * SEQ + m0 + wm + r);
    const size_t rowB = rowA + 8;
#pragma unroll
    for (int nt = 0; nt < 8; nt++) {
        const int col = h * HD + nt * 8 + (c << 1);
        *(float2*)&vals[rowA * D_MODEL + col] =
            make_float2(acc[nt][0] * invA, acc[nt][1] * invA);
        *(float2*)&vals[rowB * D_MODEL + col] =
            make_float2(acc[nt][2] * invB, acc[nt][3] * invB);
    }
}

// ---------------- out = LayerNorm(a + res) ----------------------------------
__global__ void __launch_bounds__(256) add_layernorm(const float* __restrict__ a,
                                                     const float* __restrict__ res,
                                                     const float* __restrict__ gamma,
                                                     const float* __restrict__ beta,
                                                     float* __restrict__ out) {
    __shared__ float smA[8];
    __shared__ float smB[8];
    const int row = blockIdx.x, tid = threadIdx.x;
    const float* pa = a + (size_t)row * D_MODEL;
    const float* pr = res + (size_t)row * D_MODEL;

    float v[4];
    float s = 0.f, sq = 0.f;
#pragma unroll
    for (int i = 0; i < 4; i++) {
        v[i] = pa[tid + (i << 8)] + pr[tid + (i << 8)];
        s += v[i];
        sq += v[i] * v[i];
    }
#pragma unroll
    for (int o = 16; o; o >>= 1) {
        s  += __shfl_xor_sync(0xffffffffu, s, o);
        sq += __shfl_xor_sync(0xffffffffu, sq, o);
    }
    if ((tid & 31) == 0) { smA[tid >> 5] = s; smB[tid >> 5] = sq; }
    __syncthreads();
    s  = smA[0] + smA[1] + smA[2] + smA[3] + smA[4] + smA[5] + smA[6] + smA[7];
    sq = smB[0] + smB[1] + smB[2] + smB[3] + smB[4] + smB[5] + smB[6] + smB[7];

    const float mean = s * (1.f / D_MODEL);
    const float var  = sq * (1.f / D_MODEL) - mean * mean;
    const float rstd = rsqrtf(var + 1e-5f);
#pragma unroll
    for (int i = 0; i < 4; i++) {
        const int c = tid + (i << 8);
        out[(size_t)row * D_MODEL + c] = gamma[c] * (v[i] - mean) * rstd + beta[c];
    }
}

// ---------------- launcher --------------------------------------------------
extern "C" void kernel_launch(void* const* d_in, const int* in_sizes, int n_in,
                              void* d_out, int out_size) {
    const float* x      = (const float*)d_in[0];
    const float* W_qkv  = (const float*)d_in[1];
    const float* b_qkv  = (const float*)d_in[2];
    const float* W_o    = (const float*)d_in[3];
    const float* b_o    = (const float*)d_in[4];
    const float* gamma1 = (const float*)d_in[5];
    const float* beta1  = (const float*)d_in[6];
    const float* W1     = (const float*)d_in[7];
    const float* b1     = (const float*)d_in[8];
    const float* W2     = (const float*)d_in[9];
    const float* b2     = (const float*)d_in[10];
    const float* gamma2 = (const float*)d_in[11];
    const float* beta2  = (const float*)d_in[12];
    float* out = (float*)d_out;

    float *qkv, *vals, *attn, *h, *f1, *f2;
    cudaGetSymbolAddress((void**)&qkv,  g_qkv);
    cudaGetSymbolAddress((void**)&vals, g_vals);
    cudaGetSymbolAddress((void**)&attn, g_attn);
    cudaGetSymbolAddress((void**)&h,    g_h);
    cudaGetSymbolAddress((void**)&f1,   g_ffn1);
    cudaGetSymbolAddress((void**)&f2,   g_ffn2);

    cudaFuncSetAttribute(attn_flash_mma,
                         cudaFuncAttributeMaxDynamicSharedMemorySize, ATTN_SMEM);
    cudaFuncSetAttribute(gemm_mma<false>,
                         cudaFuncAttributeMaxDynamicSharedMemorySize, GEMM_SMEM);
    cudaFuncSetAttribute(gemm_mma<true>,
                         cudaFuncAttributeMaxDynamicSharedMemorySize, GEMM_SMEM);

    // 1. qkv = x @ W_qkv + b_qkv          [4096, 3072]
    gemm_mma<false><<<dim3(QKV_LD / 128, ROWS / 128), 256, GEMM_SMEM>>>(
        x, W_qkv, b_qkv, qkv, ROWS, QKV_LD, D_MODEL);
    // 2-4. fused attention (tf32 MMA)
    attn_flash_mma<<<dim3(1, SEQ / 128, BH), 256, ATTN_SMEM>>>(qkv, vals);
    // 5. attn = vals @ W_o + b_o
    gemm_mma<false><<<dim3(D_MODEL / 128, ROWS / 128), 256, GEMM_SMEM>>>(
        vals, W_o, b_o, attn, ROWS, D_MODEL, D_MODEL);
    // 6. h = LN(attn + x)
    add_layernorm<<<ROWS, 256>>>(attn, x, gamma1, beta1, h);
    // 7. f1 = relu(h @ W1 + b1)           [4096, 4096]
    gemm_mma<true><<<dim3(FFN / 128, ROWS / 128), 256, GEMM_SMEM>>>(
        h, W1, b1, f1, ROWS, FFN, D_MODEL);
    // 8. f2 = f1 @ W2 + b2                [4096, 1024]
    gemm_mma<false><<<dim3(D_MODEL / 128, ROWS / 128), 256, GEMM_SMEM>>>(
        f1, W2, b2, f2, ROWS, D_MODEL, FFN);
    // 9. out = LN(f2 + h)
    add_layernorm<<<ROWS, 256>>>(f2, h, gamma2, beta2, out);
}

// round 13
// speedup vs baseline: 3.1570x; 1.0746x over previous
#include <cuda_runtime.h>
#include <math.h>
#include <stdint.h>

#define D_MODEL 1024
#define SEQ     2048
#define BATCH   2
#define NH      16
#define HD      64
#define FFN     4096
#define ROWS    (BATCH * SEQ)   /* 4096 */
#define BH      (BATCH * NH)    /* 32 */
#define QKV_LD  (3 * D_MODEL)   /* 3072 */

// ---------------- scratch (static device memory; no allocations) ------------
__device__ float g_qkv[ROWS * QKV_LD];                       // 50 MB
__device__ float g_vals[ROWS * D_MODEL];
__device__ float g_attn[ROWS * D_MODEL];
__device__ float g_h[ROWS * D_MODEL];
__device__ float g_ffn1[(size_t)ROWS * FFN];                 // 64 MB
__device__ float g_ffn2[ROWS * D_MODEL];

// ---------------- tf32 / async helpers --------------------------------------
// NOTE: tf32 MMA reads only the top 19 bits of each 32-bit operand; raw fp32
// bits are implicitly truncated (RZ). We skip explicit cvt.rna for speed.
__device__ __forceinline__ void mma_tf32(float* d, const uint32_t* a, const uint32_t* b) {
    asm volatile(
        "mma.sync.aligned.m16n8k8.row.col.f32.tf32.tf32.f32 "
        "{%0,%1,%2,%3}, {%4,%5,%6,%7}, {%8,%9}, {%0,%1,%2,%3};"
        : "+f"(d[0]), "+f"(d[1]), "+f"(d[2]), "+f"(d[3])
        : "r"(a[0]), "r"(a[1]), "r"(a[2]), "r"(a[3]), "r"(b[0]), "r"(b[1]));
}
__device__ __forceinline__ uint32_t smem_u32(const void* p) {
    uint32_t a;
    asm("{ .reg .u64 t; cvta.to.shared.u64 t, %1; cvt.u32.u64 %0, t; }"
        : "=r"(a) : "l"(p));
    return a;
}
__device__ __forceinline__ void cp16(uint32_t dst, const void* src) {
    asm volatile("cp.async.cg.shared.global [%0], [%1], 16;"
                 :: "r"(dst), "l"(src) : "memory");
}
__device__ __forceinline__ void cp_commit() {
    asm volatile("cp.async.commit_group;" ::: "memory");
}
template <int N>
__device__ __forceinline__ void cp_wait() {
    asm volatile("cp.async.wait_group %0;" :: "n"(N) : "memory");
}

// ---------------- tf32 GEMM, cp.async 3-stage pipeline ----------------------
// C = A[M,K] @ B[K,N] + bias (opt ReLU). CTA tile 128x128, BK=32, 8 warps
// (2x4), warp tile 64x32 (4x4 m16n8k8 frags). A smem [m][k] str36,
// B smem [k][n] str136 — both conflict-free for fragment LDS.
#define AST 36
#define BST 136
#define STG_FLOATS (128 * AST + 32 * BST)     /* 8960 floats = 35840 B */
#define GEMM_SMEM (3 * STG_FLOATS * 4)        /* 107520 B */

template <bool RELU>
__global__ void __launch_bounds__(256, 2) gemm_mma(const float* __restrict__ A,
                                                   const float* __restrict__ B,
                                                   const float* __restrict__ bias,
                                                   float* __restrict__ C,
                                                   int M, int N, int K) {
    extern __shared__ float smem[];
    const int tid = threadIdx.x;
    const int wid = tid >> 5, lane = tid & 31;
    const int bm = blockIdx.y << 7, bn = blockIdx.x << 7;
    const int wm = (wid >> 2) << 6;          // 0 or 64
    const int wn = (wid & 3) << 5;           // 0,32,64,96
    const int r = lane >> 2, c = lane & 3;
    const uint32_t smem_base = smem_u32(smem);
    const int NB = K >> 5;

    auto issue = [&](int kb) {
        if (kb < NB) {
            const uint32_t As_b = smem_base + (uint32_t)(kb % 3) * (STG_FLOATS * 4);
            const uint32_t Bs_b = As_b + 128 * AST * 4;
#pragma unroll
            for (int i = 0; i < 4; i++) {
                const int id = tid + (i << 8);
                const int row = id >> 3, kc = (id & 7) << 2;
                cp16(As_b + (uint32_t)(row * AST + kc) * 4,
                     A + (size_t)(bm + row) * K + (kb << 5) + kc);
            }
#pragma unroll
            for (int i = 0; i < 4; i++) {
                const int id = tid + (i << 8);
                const int row = id >> 5, nc = (id & 31) << 2;
                cp16(Bs_b + (uint32_t)(row * BST + nc) * 4,
                     B + (size_t)((kb << 5) + row) * N + bn + nc);
            }
        }
        cp_commit();
    };

    float acc[4][4][4] = {};

    issue(0);
    issue(1);

    for (int kb = 0; kb < NB; kb++) {
        cp_wait<1>();
        __syncthreads();
        issue(kb + 2);

        const float* As_s = smem + (kb % 3) * STG_FLOATS;
        const float* Bs_s = As_s + 128 * AST;
#pragma unroll
        for (int g = 0; g < 4; g++) {
            const int k0 = g << 3;
            uint32_t a[4][4], b[4][2];
#pragma unroll
            for (int mt = 0; mt < 4; mt++) {
                const int m = wm + (mt << 4) + r;
                a[mt][0] = __float_as_uint(As_s[m * AST + k0 + c]);
                a[mt][1] = __float_as_uint(As_s[(m + 8) * AST + k0 + c]);
                a[mt][2] = __float_as_uint(As_s[m * AST + k0 + c + 4]);
                a[mt][3] = __float_as_uint(As_s[(m + 8) * AST + k0 + c + 4]);
            }
#pragma unroll
            for (int nt = 0; nt < 4; nt++) {
                const int n = wn + (nt << 3) + r;
                b[nt][0] = __float_as_uint(Bs_s[(k0 + c) * BST + n]);
                b[nt][1] = __float_as_uint(Bs_s[(k0 + c + 4) * BST + n]);
            }
#pragma unroll
            for (int mt = 0; mt < 4; mt++)
#pragma unroll
                for (int nt = 0; nt < 4; nt++)
                    mma_tf32(acc[mt][nt], a[mt], b[nt]);
        }
    }

    // ---- epilogue: bias (+ReLU), write C ----
#pragma unroll
    for (int mt = 0; mt < 4; mt++) {
        const int row = bm + wm + (mt << 4) + r;
#pragma unroll
        for (int nt = 0; nt < 4; nt++) {
            const int col = bn + wn + (nt << 3) + (c << 1);
            const float b0 = bias[col], b1 = bias[col + 1];
            float v0 = acc[mt][nt][0] + b0;
            float v1 = acc[mt][nt][1] + b1;
            float v2 = acc[mt][nt][2] + b0;
            float v3 = acc[mt][nt][3] + b1;
            if (RELU) {
                v0 = fmaxf(v0, 0.f); v1 = fmaxf(v1, 0.f);
                v2 = fmaxf(v2, 0.f); v3 = fmaxf(v3, 0.f);
            }
            *(float2*)&C[(size_t)row * N + col] = make_float2(v0, v1);
            *(float2*)&C[(size_t)(row + 8) * N + col] = make_float2(v2, v3);
        }
    }
}

// ---------------- tf32 tensor-core flash attention ---------------------------
// Per (b,h): 128-row Q tile per CTA, 256 threads (8 warps, warp w owns rows
// 16w..16w+15). K/V streamed in 64-row tiles. Online softmax warp-local.
// All MMA operands stored as raw fp32 bits (HW tf32 truncation).
#define ATTN_SMEM ((64 * 136 + 64 * 72 + 64 * 72 + 64 * 136) * 4)
__global__ void __launch_bounds__(256) attn_flash_mma(const float* __restrict__ qkv,
                                                      float* __restrict__ vals) {
    extern __shared__ uint32_t sm[];
    uint32_t* Qs = sm;                    // [64][136]
    uint32_t* Ks = sm + 64 * 136;         // [64][72]
    uint32_t* Vs = Ks + 64 * 72;          // [64][72]
    uint32_t* Ps = Vs + 64 * 72;          // [64][136]

    const int tid = threadIdx.x;
    const int wid = tid >> 5, lane = tid & 31;
    const int r = lane >> 2, c = lane & 3;
    const int z = blockIdx.z, b = z >> 4, h = z & 15;
    const int m0 = blockIdx.y << 7;       // 128-row Q tile
    const size_t base = (size_t)b * SEQ * QKV_LD + (size_t)h * (3 * HD);
    const int wm = wid << 4;              // warp row offset 0..112

    // ---- load Q tile -> Qs[d][m], fold 1/sqrt(64) ----
    {
        const int row = tid >> 1;
        const int d0 = (tid & 1) << 5;
        const float* Qp = qkv + base + (size_t)(m0 + row) * QKV_LD + d0;
#pragma unroll
        for (int i = 0; i < 8; i++) {
            float4 q = *(const float4*)(Qp + i * 4);
            const int d = d0 + i * 4;
            Qs[(d + 0) * 136 + row] = __float_as_uint(q.x * 0.125f);
            Qs[(d + 1) * 136 + row] = __float_as_uint(q.y * 0.125f);
            Qs[(d + 2) * 136 + row] = __float_as_uint(q.z * 0.125f);
            Qs[(d + 3) * 136 + row] = __float_as_uint(q.w * 0.125f);
        }
    }

    float m_run[2] = {-1e30f, -1e30f};    // rows wm+r, wm+r+8
    float l_run[2] = {0.f, 0.f};
    float acc[8][4] = {};

    for (int kt = 0; kt < SEQ; kt += 64) {
        __syncthreads();   // prev PV done reading Vs/Ps; Q store visible (it 0)
        // ---- K tile -> Ks[d][n]; V tile -> Vs[k][n] ----
        {
            const int row = tid >> 2;            // 0..63
            const int d0 = (tid & 3) << 4;       // 0,16,32,48
            const float* Kp = qkv + base + HD + (size_t)(kt + row) * QKV_LD + d0;
            const float* Vp = qkv + base + 2 * HD + (size_t)(kt + row) * QKV_LD + d0;
#pragma unroll
            for (int i = 0; i < 4; i++) {
                float4 kv = *(const float4*)(Kp + i * 4);
                const int d = d0 + i * 4;
                Ks[(d + 0) * 72 + row] = __float_as_uint(kv.x);
                Ks[(d + 1) * 72 + row] = __float_as_uint(kv.y);
                Ks[(d + 2) * 72 + row] = __float_as_uint(kv.z);
                Ks[(d + 3) * 72 + row] = __float_as_uint(kv.w);
                *(float4*)&Vs[row * 72 + d] = *(const float4*)(Vp + i * 4);
            }
        }
        __syncthreads();

        // ---- S = (Q/8) K^T : warp rows [wm, wm+16), 8 n-tiles ----
        float s[8][4] = {};
#pragma unroll
        for (int k0 = 0; k0 < 64; k0 += 8) {
            uint32_t a[4];
            a[0] = Qs[(k0 + c) * 136 + wm + r];
            a[1] = Qs[(k0 + c) * 136 + wm + r + 8];
            a[2] = Qs[(k0 + c + 4) * 136 + wm + r];
            a[3] = Qs[(k0 + c + 4) * 136 + wm + r + 8];
#pragma unroll
            for (int nt = 0; nt < 8; nt++) {
                uint32_t bf[2];
                bf[0] = Ks[(k0 + c) * 72 + nt * 8 + r];
                bf[1] = Ks[(k0 + c + 4) * 72 + nt * 8 + r];
                mma_tf32(s[nt], a, bf);
            }
        }

        // ---- online softmax (warp-local rows) ----
        float mA = -1e30f, mB = -1e30f;
#pragma unroll
        for (int nt = 0; nt < 8; nt++) {
            mA = fmaxf(mA, fmaxf(s[nt][0], s[nt][1]));
            mB = fmaxf(mB, fmaxf(s[nt][2], s[nt][3]));
        }
        mA = fmaxf(mA, __shfl_xor_sync(0xffffffffu, mA, 1));
        mA = fmaxf(mA, __shfl_xor_sync(0xffffffffu, mA, 2));
        mB = fmaxf(mB, __shfl_xor_sync(0xffffffffu, mB, 1));
        mB = fmaxf(mB, __shfl_xor_sync(0xffffffffu, mB, 2));
        const float mnA = fmaxf(m_run[0], mA);
        const float mnB = fmaxf(m_run[1], mB);
        const float scA = __expf(m_run[0] - mnA);
        const float scB = __expf(m_run[1] - mnB);
        float rsA = 0.f, rsB = 0.f;
#pragma unroll
        for (int nt = 0; nt < 8; nt++) {
            s[nt][0] = __expf(s[nt][0] - mnA);
            s[nt][1] = __expf(s[nt][1] - mnA);
            s[nt][2] = __expf(s[nt][2] - mnB);
            s[nt][3] = __expf(s[nt][3] - mnB);
            rsA += s[nt][0] + s[nt][1];
            rsB += s[nt][2] + s[nt][3];
            acc[nt][0] *= scA; acc[nt][1] *= scA;
            acc[nt][2] *= scB; acc[nt][3] *= scB;
        }
        rsA += __shfl_xor_sync(0xffffffffu, rsA, 1);
        rsA += __shfl_xor_sync(0xffffffffu, rsA, 2);
        rsB += __shfl_xor_sync(0xffffffffu, rsB, 1);
        rsB += __shfl_xor_sync(0xffffffffu, rsB, 2);
        l_run[0] = l_run[0] * scA + rsA;
        l_run[1] = l_run[1] * scB + rsB;
        m_run[0] = mnA;
        m_run[1] = mnB;

        __syncthreads();   // prev PV reads of Ps complete (also K/V read done)

        // ---- stage P -> Ps[k][m] ----
#pragma unroll
        for (int nt = 0; nt < 8; nt++) {
            const int n = nt * 8 + (c << 1);
            Ps[(n + 0) * 136 + wm + r]     = __float_as_uint(s[nt][0]);
            Ps[(n + 1) * 136 + wm + r]     = __float_as_uint(s[nt][1]);
            Ps[(n + 0) * 136 + wm + r + 8] = __float_as_uint(s[nt][2]);
            Ps[(n + 1) * 136 + wm + r + 8] = __float_as_uint(s[nt][3]);
        }
        __syncthreads();

        // ---- O += P @ V ----
#pragma unroll
        for (int k0 = 0; k0 < 64; k0 += 8) {
            uint32_t a[4];
            a[0] = Ps[(k0 + c) * 136 + wm + r];
            a[1] = Ps[(k0 + c) * 136 + wm + r + 8];
            a[2] = Ps[(k0 + c + 4) * 136 + wm + r];
            a[3] = Ps[(k0 + c + 4) * 136 + wm + r + 8];
#pragma unroll
            for (int nt = 0; nt < 8; nt++) {
                uint32_t bf[2];
                bf[0] = Vs[(k0 + c) * 72 + nt * 8 + r];
                bf[1] = Vs[(k0 + c + 4) * 72 + nt * 8 + r];
                mma_tf32(acc[nt], a, bf);
            }
        }
    }

    // ---- finalize: divide by row sums, write [B,S,D] ----
    const float invA = 1.f / l_run[0];
    const float invB = 1.f / l_run[1];
    const size_t rowA = (size_t)(b * SEQ + m0 + wm + r);
    const size_t rowB = rowA + 8;
#pragma unroll
    for (int nt = 0; nt < 8; nt++) {
        const int col = h * HD + nt * 8 + (c << 1);
        *(float2*)&vals[rowA * D_MODEL + col] =
            make_float2(acc[nt][0] * invA, acc[nt][1] * invA);
        *(float2*)&vals[rowB * D_MODEL + col] =
            make_float2(acc[nt][2] * invB, acc[nt][3] * invB);
    }
}

// ---------------- out = LayerNorm(a + res) ----------------------------------
__global__ void __launch_bounds__(256) add_layernorm(const float* __restrict__ a,
                                                     const float* __restrict__ res,
                                                     const float* __restrict__ gamma,
                                                     const float* __restrict__ beta,
                                                     float* __restrict__ out) {
    __shared__ float smA[8];
    __shared__ float smB[8];
    const int row = blockIdx.x, tid = threadIdx.x;
    const float* pa = a + (size_t)row * D_MODEL;
    const float* pr = res + (size_t)row * D_MODEL;

    float v[4];
    float s = 0.f, sq = 0.f;
#pragma unroll
    for (int i = 0; i < 4; i++) {
        v[i] = pa[tid + (i << 8)] + pr[tid + (i << 8)];
        s += v[i];
        sq += v[i] * v[i];
    }
#pragma unroll
    for (int o = 16; o; o >>= 1) {
        s  += __shfl_xor_sync(0xffffffffu, s, o);
        sq += __shfl_xor_sync(0xffffffffu, sq, o);
    }
    if ((tid & 31) == 0) { smA[tid >> 5] = s; smB[tid >> 5] = sq; }
    __syncthreads();
    s  = smA[0] + smA[1] + smA[2] + smA[3] + smA[4] + smA[5] + smA[6] + smA[7];
    sq = smB[0] + smB[1] + smB[2] + smB[3] + smB[4] + smB[5] + smB[6] + smB[7];

    const float mean = s * (1.f / D_MODEL);
    const float var  = sq * (1.f / D_MODEL) - mean * mean;
    const float rstd = rsqrtf(var + 1e-5f);
#pragma unroll
    for (int i = 0; i < 4; i++) {
        const int c = tid + (i << 8);
        out[(size_t)row * D_MODEL + c] = gamma[c] * (v[i] - mean) * rstd + beta[c];
    }
}

// ---------------- launcher --------------------------------------------------
extern "C" void kernel_launch(void* const* d_in, const int* in_sizes, int n_in,
                              void* d_out, int out_size) {
    const float* x      = (const float*)d_in[0];
    const float* W_qkv  = (const float*)d_in[1];
    const float* b_qkv  = (const float*)d_in[2];
    const float* W_o    = (const float*)d_in[3];
    const float* b_o    = (const float*)d_in[4];
    const float* gamma1 = (const float*)d_in[5];
    const float* beta1  = (const float*)d_in[6];
    const float* W1     = (const float*)d_in[7];
    const float* b1     = (const float*)d_in[8];
    const float* W2     = (const float*)d_in[9];
    const float* b2     = (const float*)d_in[10];
    const float* gamma2 = (const float*)d_in[11];
    const float* beta2  = (const float*)d_in[12];
    float* out = (float*)d_out;

    float *qkv, *vals, *attn, *h, *f1, *f2;
    cudaGetSymbolAddress((void**)&qkv,  g_qkv);
    cudaGetSymbolAddress((void**)&vals, g_vals);
    cudaGetSymbolAddress((void**)&attn, g_attn);
    cudaGetSymbolAddress((void**)&h,    g_h);
    cudaGetSymbolAddress((void**)&f1,   g_ffn1);
    cudaGetSymbolAddress((void**)&f2,   g_ffn2);

    cudaFuncSetAttribute(attn_flash_mma,
                         cudaFuncAttributeMaxDynamicSharedMemorySize, ATTN_SMEM);
    cudaFuncSetAttribute(gemm_mma<false>,
                         cudaFuncAttributeMaxDynamicSharedMemorySize, GEMM_SMEM);
    cudaFuncSetAttribute(gemm_mma<true>,
                         cudaFuncAttributeMaxDynamicSharedMemorySize, GEMM_SMEM);

    // 1. qkv = x @ W_qkv + b_qkv          [4096, 3072]
    gemm_mma<false><<<dim3(QKV_LD / 128, ROWS / 128), 256, GEMM_SMEM>>>(
        x, W_qkv, b_qkv, qkv, ROWS, QKV_LD, D_MODEL);
    // 2-4. fused attention (tf32 MMA)
    attn_flash_mma<<<dim3(1, SEQ / 128, BH), 256, ATTN_SMEM>>>(qkv, vals);
    // 5. attn = vals @ W_o + b_o
    gemm_mma<false><<<dim3(D_MODEL / 128, ROWS / 128), 256, GEMM_SMEM>>>(
        vals, W_o, b_o, attn, ROWS, D_MODEL, D_MODEL);
    // 6. h = LN(attn + x)
    add_layernorm<<<ROWS, 256>>>(attn, x, gamma1, beta1, h);
    // 7. f1 = relu(h @ W1 + b1)           [4096, 4096]
    gemm_mma<true><<<dim3(FFN / 128, ROWS / 128), 256, GEMM_SMEM>>>(
        h, W1, b1, f1, ROWS, FFN, D_MODEL);
    // 8. f2 = f1 @ W2 + b2                [4096, 1024]
    gemm_mma<false><<<dim3(D_MODEL / 128, ROWS / 128), 256, GEMM_SMEM>>>(
        f1, W2, b2, f2, ROWS, D_MODEL, FFN);
    // 9. out = LN(f2 + h)
    add_layernorm<<<ROWS, 256>>>(f2, h, gamma2, beta2, out);
}